// round 2
// baseline (speedup 1.0000x reference)
#include <cuda_runtime.h>
#include <math.h>

#define N_NODES 50000
#define N_EDGES 800000
#define D       128
#define DE      10
#define K_IN    266            // 2*D + DE
#define TILE_E  32
#define KC      14             // 266 = 19 * 14
#define NCHUNK  19
#define ZSTRIDE 268            // padded row stride for Z tile (mult of 4)
#define BN_EPS  1e-5f

// Scratch (device globals: allocation-free)
__device__ float  g_agg[N_NODES * D];
__device__ double g_sum[D];
__device__ double g_sumsq[D];
__device__ int    g_is64;      // 1 if edge_index is int64, 0 if int32

__device__ __forceinline__ float softplus_f(float x) {
    return fmaxf(x, 0.0f) + log1pf(__expf(-fabsf(x)));
}
__device__ __forceinline__ float sigmoid_f(float x) {
    return 1.0f / (1.0f + __expf(-x));
}

// ---------------------------------------------------------------------------
// Kernel 0: detect edge_index dtype. For little-endian int64 with values
// < 2^31, every odd 32-bit word is 0. For int32 data those words are real
// node indices (uniform in [0, 50000)), so all-64-zero is impossible.
// ---------------------------------------------------------------------------
__global__ void detect_kernel(const int* __restrict__ ei32) {
    if (threadIdx.x == 0 && blockIdx.x == 0) {
        int nz = 0;
        #pragma unroll
        for (int i = 0; i < 64; ++i)
            nz |= ei32[2 * i + 1];
        g_is64 = (nz == 0) ? 1 : 0;
    }
}

// ---------------------------------------------------------------------------
// Kernel 1: zero the aggregation buffer + stat accumulators
// ---------------------------------------------------------------------------
__global__ void zero_kernel() {
    int idx = blockIdx.x * blockDim.x + threadIdx.x;
    const int total = N_NODES * D;
    for (int i = idx; i < total; i += gridDim.x * blockDim.x)
        g_agg[i] = 0.0f;
    if (blockIdx.x == 0 && threadIdx.x < D) {
        g_sum[threadIdx.x]   = 0.0;
        g_sumsq[threadIdx.x] = 0.0;
    }
}

__device__ __forceinline__ int load_index(const void* ei, int pos, int is64) {
    if (is64) return (int)((const long long*)ei)[pos];
    return ((const int*)ei)[pos];
}

// ---------------------------------------------------------------------------
// Kernel 2: edge GEMM + gating + scatter-add
//   Z[e,:] = [h[src], h[dst], edge_feat]  (K=266)
//   out cols 0..127 = gate (sigmoid), 128..255 = cand (softplus)
//   m = g*c scattered to g_agg[src]
// Block: 256 threads = (tx 0..15) x (ty 0..15); TILE_E=32 edges/block.
// ---------------------------------------------------------------------------
__global__ __launch_bounds__(256) void edge_kernel(
    const float* __restrict__ h,
    const void*  __restrict__ ei,        // [2, E] int32 or int64
    const float* __restrict__ ef,        // [E, DE]
    const float* __restrict__ gw,        // [K_IN, D]
    const float* __restrict__ gb,        // [D]
    const float* __restrict__ cw,        // [K_IN, D]
    const float* __restrict__ cb)        // [D]
{
    __shared__ float Zs[TILE_E * ZSTRIDE];   // 34304 B
    __shared__ float Ws[KC * 256];           // 14336 B
    __shared__ int   Ssrc[TILE_E];           //   128 B

    const int tid  = threadIdx.x;
    const int wid  = tid >> 5;
    const int lane = tid & 31;
    const int e0   = blockIdx.x * TILE_E;
    const int is64 = g_is64;

    // ---- Load Z tile: each warp loads 4 edges (one full row per pass) ----
    #pragma unroll
    for (int t = 0; t < TILE_E / 8; ++t) {
        int e = t * 8 + wid;
        int edge = e0 + e;
        if (edge < N_EDGES) {
            int src = load_index(ei, edge, is64);
            int dst = load_index(ei, N_EDGES + edge, is64);
            float4 hs = ((const float4*)(h + (long long)src * D))[lane];
            *(float4*)&Zs[e * ZSTRIDE + lane * 4] = hs;
            float4 hd = ((const float4*)(h + (long long)dst * D))[lane];
            *(float4*)&Zs[e * ZSTRIDE + 128 + lane * 4] = hd;
            if (lane < DE)
                Zs[e * ZSTRIDE + 256 + lane] = ef[(long long)edge * DE + lane];
            if (lane == 0)
                Ssrc[e] = src;
        }
    }
    __syncthreads();

    const int tx = tid & 15;
    const int ty = tid >> 4;

    float acc[2][16];
    #pragma unroll
    for (int e = 0; e < 2; ++e)
        #pragma unroll
        for (int j = 0; j < 16; ++j)
            acc[e][j] = 0.0f;

    // ---- Main loop over K in chunks of KC ----
    for (int c = 0; c < NCHUNK; ++c) {
        const int kc = c * KC;
        #pragma unroll
        for (int kk = 0; kk < KC; ++kk) {
            int k = kc + kk;
            Ws[kk * 256 + tid] = (tid < 128) ? gw[k * D + tid]
                                             : cw[k * D + (tid - 128)];
        }
        __syncthreads();

        #pragma unroll
        for (int kk = 0; kk < KC; ++kk) {
            const float* wrow = &Ws[kk * 256];
            float4 w0 = *(const float4*)&wrow[      tx * 4];
            float4 w1 = *(const float4*)&wrow[ 64 + tx * 4];
            float4 w2 = *(const float4*)&wrow[128 + tx * 4];
            float4 w3 = *(const float4*)&wrow[192 + tx * 4];
            float z0 = Zs[(ty * 2 + 0) * ZSTRIDE + kc + kk];
            float z1 = Zs[(ty * 2 + 1) * ZSTRIDE + kc + kk];

            acc[0][0]  += z0 * w0.x;  acc[0][1]  += z0 * w0.y;
            acc[0][2]  += z0 * w0.z;  acc[0][3]  += z0 * w0.w;
            acc[0][4]  += z0 * w1.x;  acc[0][5]  += z0 * w1.y;
            acc[0][6]  += z0 * w1.z;  acc[0][7]  += z0 * w1.w;
            acc[0][8]  += z0 * w2.x;  acc[0][9]  += z0 * w2.y;
            acc[0][10] += z0 * w2.z;  acc[0][11] += z0 * w2.w;
            acc[0][12] += z0 * w3.x;  acc[0][13] += z0 * w3.y;
            acc[0][14] += z0 * w3.z;  acc[0][15] += z0 * w3.w;

            acc[1][0]  += z1 * w0.x;  acc[1][1]  += z1 * w0.y;
            acc[1][2]  += z1 * w0.z;  acc[1][3]  += z1 * w0.w;
            acc[1][4]  += z1 * w1.x;  acc[1][5]  += z1 * w1.y;
            acc[1][6]  += z1 * w1.z;  acc[1][7]  += z1 * w1.w;
            acc[1][8]  += z1 * w2.x;  acc[1][9]  += z1 * w2.y;
            acc[1][10] += z1 * w2.z;  acc[1][11] += z1 * w2.w;
            acc[1][12] += z1 * w3.x;  acc[1][13] += z1 * w3.y;
            acc[1][14] += z1 * w3.z;  acc[1][15] += z1 * w3.w;
        }
        __syncthreads();
    }

    // ---- Epilogue: bias + sigmoid/softplus + scatter-add ----
    #pragma unroll
    for (int e = 0; e < 2; ++e) {
        int edge = e0 + ty * 2 + e;
        if (edge < N_EDGES) {
            int src = Ssrc[ty * 2 + e];
            float* aggp = g_agg + (long long)src * D;
            #pragma unroll
            for (int j = 0; j < 2; ++j) {
                #pragma unroll
                for (int i = 0; i < 4; ++i) {
                    int d = j * 64 + tx * 4 + i;
                    float gv = sigmoid_f(acc[e][j * 4 + i] + gb[d]);
                    float cv = softplus_f(acc[e][(j + 2) * 4 + i] + cb[d]);
                    atomicAdd(aggp + d, gv * cv);
                }
            }
        }
    }
}

// ---------------------------------------------------------------------------
// Kernel 3: BN stats (column mean / sumsq over 50000 rows), fp64 accumulate
// ---------------------------------------------------------------------------
__global__ void stats_kernel() {
    int d = threadIdx.x;   // blockDim = 128
    double s = 0.0, s2 = 0.0;
    for (int n = blockIdx.x; n < N_NODES; n += gridDim.x) {
        float v = g_agg[n * D + d];
        s  += (double)v;
        s2 += (double)v * (double)v;
    }
    atomicAdd(&g_sum[d], s);
    atomicAdd(&g_sumsq[d], s2);
}

// ---------------------------------------------------------------------------
// Kernel 4: BN normalize + residual + softplus
// ---------------------------------------------------------------------------
__global__ void final_kernel(const float* __restrict__ h,
                             const float* __restrict__ gamma,
                             const float* __restrict__ beta,
                             float* __restrict__ out) {
    const int total = N_NODES * D;
    for (int idx = blockIdx.x * blockDim.x + threadIdx.x; idx < total;
         idx += gridDim.x * blockDim.x) {
        int d = idx & (D - 1);
        double mean = g_sum[d] * (1.0 / N_NODES);
        double var  = g_sumsq[d] * (1.0 / N_NODES) - mean * mean;
        float invstd = rsqrtf((float)var + BN_EPS);
        float x = h[idx] + (g_agg[idx] - (float)mean) * invstd * gamma[d] + beta[d];
        out[idx] = softplus_f(x);
    }
}

// ---------------------------------------------------------------------------
extern "C" void kernel_launch(void* const* d_in, const int* in_sizes, int n_in,
                              void* d_out, int out_size) {
    const float* h     = (const float*)d_in[0];
    const void*  ei    = d_in[1];
    const float* ef    = (const float*)d_in[2];
    const float* gw    = (const float*)d_in[3];
    const float* gb    = (const float*)d_in[4];
    const float* cw    = (const float*)d_in[5];
    const float* cb    = (const float*)d_in[6];
    const float* gamma = (const float*)d_in[7];
    const float* beta  = (const float*)d_in[8];
    float* out = (float*)d_out;

    detect_kernel<<<1, 32>>>((const int*)ei);
    zero_kernel<<<512, 256>>>();
    edge_kernel<<<(N_EDGES + TILE_E - 1) / TILE_E, 256>>>(h, ei, ef, gw, gb, cw, cb);
    stats_kernel<<<256, 128>>>();
    final_kernel<<<512, 256>>>(h, gamma, beta, out);
}

// round 3
// speedup vs baseline: 5.9083x; 5.9083x over previous
#include <cuda_runtime.h>
#include <math.h>

#define N_NODES 50000
#define N_EDGES 800000
#define D       128
#define DE      10
#define BN_EPS  1e-5f

// Scratch (device globals: allocation-free)
// P layout per node: [0:128) g1=h@gw[0:128]+gb, [128:256) c1=h@cw[0:128]+cb,
//                    [256:384) g2=h@gw[128:256], [384:512) c2=h@cw[128:256]
__device__ float  g_P[N_NODES * 512];
__device__ float  g_agg[N_NODES * D];
__device__ double g_sum[D];
__device__ double g_sumsq[D];
__device__ float  g_a[D];     // invstd*gamma
__device__ float  g_b[D];     // beta - mean*invstd*gamma
__device__ int    g_is64;

__device__ __forceinline__ float softplus_f(float x) {
    return fmaxf(x, 0.0f) + __logf(1.0f + __expf(-fabsf(x)));
}
__device__ __forceinline__ float sigmoid_f(float x) {
    return 1.0f / (1.0f + __expf(-x));
}

// ---------------------------------------------------------------------------
// Kernel 0: detect edge_index dtype (int64 little-endian -> odd words all 0)
// ---------------------------------------------------------------------------
__global__ void detect_kernel(const int* __restrict__ ei32) {
    if (threadIdx.x == 0 && blockIdx.x == 0) {
        int nz = 0;
        #pragma unroll
        for (int i = 0; i < 64; ++i) nz |= ei32[2 * i + 1];
        g_is64 = (nz == 0) ? 1 : 0;
    }
}

// ---------------------------------------------------------------------------
// Kernel 1: zero agg + stat accumulators (vectorized)
// ---------------------------------------------------------------------------
__global__ void zero_kernel() {
    int idx = blockIdx.x * blockDim.x + threadIdx.x;
    const int total4 = N_NODES * D / 4;
    float4 z = make_float4(0.f, 0.f, 0.f, 0.f);
    for (int i = idx; i < total4; i += gridDim.x * blockDim.x)
        ((float4*)g_agg)[i] = z;
    if (blockIdx.x == 0 && threadIdx.x < D) {
        g_sum[threadIdx.x] = 0.0;
        g_sumsq[threadIdx.x] = 0.0;
    }
}

// ---------------------------------------------------------------------------
// Kernel 2: node projection GEMM.
// blockIdx.y = quadrant q: (q&1 ? cw : gw), k-offset (q>>1)*128, bias on q<2.
// CTA tile: 64 rows x 128 cols, K=128 in chunks of 16.
// Block 256 thr: tx=tid&31 (col grp of 4), ty=tid>>5 (8 rows), acc[8][4].
// ---------------------------------------------------------------------------
__global__ __launch_bounds__(256) void node_gemm(
    const float* __restrict__ h,
    const float* __restrict__ gw, const float* __restrict__ cw,
    const float* __restrict__ gb, const float* __restrict__ cb)
{
    __shared__ float Hs[16][72];    // [kk][row], padded
    __shared__ float Ws[16][128];

    const int q    = blockIdx.y;
    const float* W = (q & 1) ? cw : gw;
    const int koff = (q >> 1) * 128;
    const int row0 = blockIdx.x * 64;
    const int tid  = threadIdx.x;
    const int tx   = tid & 31, ty = tid >> 5;

    float acc[8][4];
    #pragma unroll
    for (int i = 0; i < 8; ++i)
        #pragma unroll
        for (int c = 0; c < 4; ++c) acc[i][c] = 0.f;

    for (int kc = 0; kc < 128; kc += 16) {
        // stage H^T chunk
        {
            int r = tid >> 2, c4 = (tid & 3) * 4;
            float4 v = make_float4(0.f, 0.f, 0.f, 0.f);
            if (row0 + r < N_NODES)
                v = *(const float4*)&h[(size_t)(row0 + r) * 128 + kc + c4];
            Hs[c4 + 0][r] = v.x; Hs[c4 + 1][r] = v.y;
            Hs[c4 + 2][r] = v.z; Hs[c4 + 3][r] = v.w;
        }
        // stage W chunk
        #pragma unroll
        for (int j = 0; j < 2; ++j) {
            int f4 = tid + j * 256;
            int kk = f4 >> 5, c4 = (f4 & 31) * 4;
            *(float4*)&Ws[kk][c4] =
                *(const float4*)&W[(size_t)(koff + kc + kk) * 128 + c4];
        }
        __syncthreads();

        #pragma unroll
        for (int kk = 0; kk < 16; ++kk) {
            float4 wv = *(float4*)&Ws[kk][tx * 4];
            float4 h0 = *(float4*)&Hs[kk][ty * 8];
            float4 h1 = *(float4*)&Hs[kk][ty * 8 + 4];
            float hv[8] = {h0.x, h0.y, h0.z, h0.w, h1.x, h1.y, h1.z, h1.w};
            #pragma unroll
            for (int i = 0; i < 8; ++i) {
                acc[i][0] += hv[i] * wv.x; acc[i][1] += hv[i] * wv.y;
                acc[i][2] += hv[i] * wv.z; acc[i][3] += hv[i] * wv.w;
            }
        }
        __syncthreads();
    }

    float4 bv = make_float4(0.f, 0.f, 0.f, 0.f);
    if (q == 0)      bv = *(const float4*)&gb[tx * 4];
    else if (q == 1) bv = *(const float4*)&cb[tx * 4];

    #pragma unroll
    for (int i = 0; i < 8; ++i) {
        int r = row0 + ty * 8 + i;
        if (r < N_NODES) {
            float4 v = make_float4(acc[i][0] + bv.x, acc[i][1] + bv.y,
                                   acc[i][2] + bv.z, acc[i][3] + bv.w);
            *(float4*)&g_P[(size_t)r * 512 + q * 128 + tx * 4] = v;
        }
    }
}

// ---------------------------------------------------------------------------
// Kernel 3: edge stage — gather P, rank-10 edge-feature update (W3 in regs),
// activations, vectorized scatter-add.  One warp per edge, grid-stride.
// ---------------------------------------------------------------------------
__global__ __launch_bounds__(128) void edge_kernel(
    const void*  __restrict__ ei,
    const float* __restrict__ ef,
    const float* __restrict__ gw, const float* __restrict__ cw)
{
    const int lane   = threadIdx.x & 31;
    const int warp   = (blockIdx.x * blockDim.x + threadIdx.x) >> 5;
    const int nwarps = (gridDim.x * blockDim.x) >> 5;
    const int is64   = g_is64;

    // W3 rows (edge-feature weights) live in registers: 80 regs
    float4 wg[DE], wc[DE];
    #pragma unroll
    for (int k = 0; k < DE; ++k) {
        wg[k] = *(const float4*)&gw[(size_t)(256 + k) * 128 + lane * 4];
        wc[k] = *(const float4*)&cw[(size_t)(256 + k) * 128 + lane * 4];
    }

    for (int e = warp; e < N_EDGES; e += nwarps) {
        int src, dst;
        if (is64) {
            src = (int)((const long long*)ei)[e];
            dst = (int)((const long long*)ei)[N_EDGES + e];
        } else {
            src = ((const int*)ei)[e];
            dst = ((const int*)ei)[N_EDGES + e];
        }
        const float4* ps = (const float4*)(g_P + (size_t)src * 512);
        const float4* pd = (const float4*)(g_P + (size_t)dst * 512);
        float4 ag = ps[lane];         // g1 (+gb)
        float4 ac = ps[32 + lane];    // c1 (+cb)
        float4 bg = pd[64 + lane];    // g2
        float4 bc = pd[96 + lane];    // c2

        float ev = (lane < DE) ? ef[(size_t)e * DE + lane] : 0.f;

        float4 gp = make_float4(ag.x + bg.x, ag.y + bg.y, ag.z + bg.z, ag.w + bg.w);
        float4 cp = make_float4(ac.x + bc.x, ac.y + bc.y, ac.z + bc.z, ac.w + bc.w);

        #pragma unroll
        for (int k = 0; k < DE; ++k) {
            float ek = __shfl_sync(0xffffffffu, ev, k);
            gp.x += ek * wg[k].x; gp.y += ek * wg[k].y;
            gp.z += ek * wg[k].z; gp.w += ek * wg[k].w;
            cp.x += ek * wc[k].x; cp.y += ek * wc[k].y;
            cp.z += ek * wc[k].z; cp.w += ek * wc[k].w;
        }

        float4 m;
        m.x = sigmoid_f(gp.x) * softplus_f(cp.x);
        m.y = sigmoid_f(gp.y) * softplus_f(cp.y);
        m.z = sigmoid_f(gp.z) * softplus_f(cp.z);
        m.w = sigmoid_f(gp.w) * softplus_f(cp.w);

        float* out = g_agg + (size_t)src * D + lane * 4;
        asm volatile("red.global.add.v4.f32 [%0], {%1,%2,%3,%4};"
                     :: "l"(out), "f"(m.x), "f"(m.y), "f"(m.z), "f"(m.w)
                     : "memory");
    }
}

// ---------------------------------------------------------------------------
// Kernel 4: BN stats (fp64 accumulate), high-occupancy grid
// ---------------------------------------------------------------------------
__global__ void stats_kernel() {
    int d = threadIdx.x;   // blockDim = 128
    double s = 0.0, s2 = 0.0;
    for (int n = blockIdx.x; n < N_NODES; n += gridDim.x) {
        float v = g_agg[(size_t)n * D + d];
        s  += (double)v;
        s2 += (double)v * (double)v;
    }
    atomicAdd(&g_sum[d], s);
    atomicAdd(&g_sumsq[d], s2);
}

// ---------------------------------------------------------------------------
// Kernel 5: fold BN stats into per-channel affine (a, b)
// ---------------------------------------------------------------------------
__global__ void stats_final(const float* __restrict__ gamma,
                            const float* __restrict__ beta) {
    int d = threadIdx.x;   // 128 threads, 1 block
    double mean = g_sum[d] * (1.0 / N_NODES);
    double var  = g_sumsq[d] * (1.0 / N_NODES) - mean * mean;
    float invstd = rsqrtf((float)var + BN_EPS);
    float a = invstd * gamma[d];
    g_a[d] = a;
    g_b[d] = beta[d] - (float)mean * a;
}

// ---------------------------------------------------------------------------
// Kernel 6: BN apply + residual + softplus (vectorized)
// ---------------------------------------------------------------------------
__global__ void final_kernel(const float* __restrict__ h,
                             float* __restrict__ out) {
    const int total4 = N_NODES * D / 4;
    for (int f4 = blockIdx.x * blockDim.x + threadIdx.x; f4 < total4;
         f4 += gridDim.x * blockDim.x) {
        int d4 = (f4 & 31) * 4;
        float4 av = ((const float4*)g_agg)[f4];
        float4 hv = ((const float4*)h)[f4];
        float4 aa = *(const float4*)&g_a[d4];
        float4 bb = *(const float4*)&g_b[d4];
        float4 r;
        r.x = softplus_f(hv.x + av.x * aa.x + bb.x);
        r.y = softplus_f(hv.y + av.y * aa.y + bb.y);
        r.z = softplus_f(hv.z + av.z * aa.z + bb.z);
        r.w = softplus_f(hv.w + av.w * aa.w + bb.w);
        ((float4*)out)[f4] = r;
    }
}

// ---------------------------------------------------------------------------
extern "C" void kernel_launch(void* const* d_in, const int* in_sizes, int n_in,
                              void* d_out, int out_size) {
    const float* h     = (const float*)d_in[0];
    const void*  ei    = d_in[1];
    const float* ef    = (const float*)d_in[2];
    const float* gw    = (const float*)d_in[3];
    const float* gb    = (const float*)d_in[4];
    const float* cw    = (const float*)d_in[5];
    const float* cb    = (const float*)d_in[6];
    const float* gamma = (const float*)d_in[7];
    const float* beta  = (const float*)d_in[8];
    float* out = (float*)d_out;

    detect_kernel<<<1, 32>>>((const int*)ei);
    zero_kernel<<<1024, 256>>>();
    dim3 gg((N_NODES + 63) / 64, 4);
    node_gemm<<<gg, 256>>>(h, gw, cw, gb, cb);
    edge_kernel<<<2048, 128>>>(ei, ef, gw, cw);
    stats_kernel<<<2048, 128>>>();
    stats_final<<<1, 128>>>(gamma, beta);
    final_kernel<<<1024, 256>>>(h, out);
}

// round 4
// speedup vs baseline: 6.1280x; 1.0372x over previous
#include <cuda_runtime.h>
#include <cuda_fp16.h>
#include <math.h>

#define N_NODES 50000
#define N_EDGES 800000
#define D       128
#define DE      10
#define BN_EPS  1e-5f

typedef unsigned long long ull;

// Scratch (device globals: allocation-free)
// P16 layout per node (512 halves): [0:128) g1=h@gw[0:128]+gb,
// [128:256) c1=h@cw[0:128]+cb, [256:384) g2=h@gw[128:256], [384:512) c2
__device__ __half  g_P16[N_NODES * 512];
__device__ float   g_agg[N_NODES * D];
__device__ double  g_sum[D];
__device__ double  g_sumsq[D];
__device__ float   g_a[D];     // invstd*gamma
__device__ float   g_b[D];     // beta - mean*invstd*gamma
__device__ int     g_is64;

// ---- packed f32x2 helpers (Blackwell FFMA2 path, PTX-only) ----
__device__ __forceinline__ ull pack2(float lo, float hi) {
    ull r; asm("mov.b64 %0, {%1, %2};" : "=l"(r) : "f"(lo), "f"(hi)); return r;
}
__device__ __forceinline__ void unpack2(ull v, float& lo, float& hi) {
    asm("mov.b64 {%0, %1}, %2;" : "=f"(lo), "=f"(hi) : "l"(v));
}
__device__ __forceinline__ ull fma2(ull a, ull b, ull c) {
    ull d; asm("fma.rn.f32x2 %0, %1, %2, %3;" : "=l"(d) : "l"(a), "l"(b), "l"(c));
    return d;
}
__device__ __forceinline__ ull add2(ull a, ull b) {
    ull d; asm("add.rn.f32x2 %0, %1, %2;" : "=l"(d) : "l"(a), "l"(b));
    return d;
}

__device__ __forceinline__ float softplus_f(float x) {
    return fmaxf(x, 0.0f) + __logf(1.0f + __expf(-fabsf(x)));
}
__device__ __forceinline__ float sigmoid_f(float x) {
    return 1.0f / (1.0f + __expf(-x));
}

// ---------------------------------------------------------------------------
// Kernel 0: detect edge_index dtype (int64 little-endian -> odd words all 0)
// ---------------------------------------------------------------------------
__global__ void detect_kernel(const int* __restrict__ ei32) {
    if (threadIdx.x == 0 && blockIdx.x == 0) {
        int nz = 0;
        #pragma unroll
        for (int i = 0; i < 64; ++i) nz |= ei32[2 * i + 1];
        g_is64 = (nz == 0) ? 1 : 0;
    }
}

// ---------------------------------------------------------------------------
// Kernel 1: zero agg + stat accumulators
// ---------------------------------------------------------------------------
__global__ void zero_kernel() {
    int idx = blockIdx.x * blockDim.x + threadIdx.x;
    const int total4 = N_NODES * D / 4;
    float4 z = make_float4(0.f, 0.f, 0.f, 0.f);
    for (int i = idx; i < total4; i += gridDim.x * blockDim.x)
        ((float4*)g_agg)[i] = z;
    if (blockIdx.x == 0 && threadIdx.x < D) {
        g_sum[threadIdx.x] = 0.0;
        g_sumsq[threadIdx.x] = 0.0;
    }
}

// ---------------------------------------------------------------------------
// Kernel 2: node projection GEMM (fp32 compute, fp16 store), f32x2 inner loop.
// blockIdx.y = quadrant q. CTA tile 64 rows x 128 cols, K chunks of 16.
// ---------------------------------------------------------------------------
__global__ __launch_bounds__(256) void node_gemm(
    const float* __restrict__ h,
    const float* __restrict__ gw, const float* __restrict__ cw,
    const float* __restrict__ gb, const float* __restrict__ cb)
{
    __shared__ float Hs[16][72];
    __shared__ float Ws[16][128];

    const int q    = blockIdx.y;
    const float* W = (q & 1) ? cw : gw;
    const int koff = (q >> 1) * 128;
    const int row0 = blockIdx.x * 64;
    const int tid  = threadIdx.x;
    const int tx   = tid & 31, ty = tid >> 5;

    ull acc2[4][4];   // [row-pair][col]
    #pragma unroll
    for (int p = 0; p < 4; ++p)
        #pragma unroll
        for (int c = 0; c < 4; ++c) acc2[p][c] = 0ull;

    for (int kc = 0; kc < 128; kc += 16) {
        {
            int r = tid >> 2, c4 = (tid & 3) * 4;
            float4 v = make_float4(0.f, 0.f, 0.f, 0.f);
            if (row0 + r < N_NODES)
                v = *(const float4*)&h[(size_t)(row0 + r) * 128 + kc + c4];
            Hs[c4 + 0][r] = v.x; Hs[c4 + 1][r] = v.y;
            Hs[c4 + 2][r] = v.z; Hs[c4 + 3][r] = v.w;
        }
        #pragma unroll
        for (int j = 0; j < 2; ++j) {
            int f4 = tid + j * 256;
            int kk = f4 >> 5, c4 = (f4 & 31) * 4;
            *(float4*)&Ws[kk][c4] =
                *(const float4*)&W[(size_t)(koff + kc + kk) * 128 + c4];
        }
        __syncthreads();

        #pragma unroll
        for (int kk = 0; kk < 16; ++kk) {
            float4 wv = *(float4*)&Ws[kk][tx * 4];
            float4 h0 = *(float4*)&Hs[kk][ty * 8];
            float4 h1 = *(float4*)&Hs[kk][ty * 8 + 4];
            ull wd[4] = {pack2(wv.x, wv.x), pack2(wv.y, wv.y),
                         pack2(wv.z, wv.z), pack2(wv.w, wv.w)};
            ull hp[4] = {pack2(h0.x, h0.y), pack2(h0.z, h0.w),
                         pack2(h1.x, h1.y), pack2(h1.z, h1.w)};
            #pragma unroll
            for (int p = 0; p < 4; ++p)
                #pragma unroll
                for (int c = 0; c < 4; ++c)
                    acc2[p][c] = fma2(hp[p], wd[c], acc2[p][c]);
        }
        __syncthreads();
    }

    float4 bv = make_float4(0.f, 0.f, 0.f, 0.f);
    if (q == 0)      bv = *(const float4*)&gb[tx * 4];
    else if (q == 1) bv = *(const float4*)&cb[tx * 4];

    #pragma unroll
    for (int p = 0; p < 4; ++p) {
        float v0[4], v1[4];   // rows 2p, 2p+1
        #pragma unroll
        for (int c = 0; c < 4; ++c) unpack2(acc2[p][c], v0[c], v1[c]);
        #pragma unroll
        for (int s = 0; s < 2; ++s) {
            int r = row0 + ty * 8 + 2 * p + s;
            if (r < N_NODES) {
                float* v = s ? v1 : v0;
                __half2 a = __floats2half2_rn(v[0] + bv.x, v[1] + bv.y);
                __half2 b = __floats2half2_rn(v[2] + bv.z, v[3] + bv.w);
                uint2 st = make_uint2(*(unsigned*)&a, *(unsigned*)&b);
                *(uint2*)&g_P16[(size_t)r * 512 + q * 128 + tx * 4] = st;
            }
        }
    }
}

// ---------------------------------------------------------------------------
// Kernel 3: edge stage — fp16 gather of P, f32x2 rank-10 update (W3 in regs),
// activations, vectorized scatter-add. One warp per edge, grid-stride.
// ---------------------------------------------------------------------------
__global__ __launch_bounds__(128) void edge_kernel(
    const void*  __restrict__ ei,
    const float* __restrict__ ef,
    const float* __restrict__ gw, const float* __restrict__ cw)
{
    const int lane   = threadIdx.x & 31;
    const int warp   = (blockIdx.x * blockDim.x + threadIdx.x) >> 5;
    const int nwarps = (gridDim.x * blockDim.x) >> 5;
    const int is64   = g_is64;

    // W3 rows in registers, packed f32x2: 80 regs
    ull wg2[DE][2], wc2[DE][2];
    #pragma unroll
    for (int k = 0; k < DE; ++k) {
        float4 tg = *(const float4*)&gw[(size_t)(256 + k) * 128 + lane * 4];
        float4 tc = *(const float4*)&cw[(size_t)(256 + k) * 128 + lane * 4];
        wg2[k][0] = pack2(tg.x, tg.y); wg2[k][1] = pack2(tg.z, tg.w);
        wc2[k][0] = pack2(tc.x, tc.y); wc2[k][1] = pack2(tc.z, tc.w);
    }

    for (int e = warp; e < N_EDGES; e += nwarps) {
        int src, dst;
        if (is64) {
            src = (int)((const long long*)ei)[e];
            dst = (int)((const long long*)ei)[N_EDGES + e];
        } else {
            src = ((const int*)ei)[e];
            dst = ((const int*)ei)[N_EDGES + e];
        }
        const __half* ps = g_P16 + (size_t)src * 512;
        const __half* pd = g_P16 + (size_t)dst * 512;

        uint2 ug1 = *(const uint2*)(ps + lane * 4);
        uint2 uc1 = *(const uint2*)(ps + 128 + lane * 4);
        uint2 ug2 = *(const uint2*)(pd + 256 + lane * 4);
        uint2 uc2 = *(const uint2*)(pd + 384 + lane * 4);

        float2 g1a = __half22float2(*(__half2*)&ug1.x);
        float2 g1b = __half22float2(*(__half2*)&ug1.y);
        float2 c1a = __half22float2(*(__half2*)&uc1.x);
        float2 c1b = __half22float2(*(__half2*)&uc1.y);
        float2 g2a = __half22float2(*(__half2*)&ug2.x);
        float2 g2b = __half22float2(*(__half2*)&ug2.y);
        float2 c2a = __half22float2(*(__half2*)&uc2.x);
        float2 c2b = __half22float2(*(__half2*)&uc2.y);

        ull gp0 = add2(pack2(g1a.x, g1a.y), pack2(g2a.x, g2a.y));
        ull gp1 = add2(pack2(g1b.x, g1b.y), pack2(g2b.x, g2b.y));
        ull cp0 = add2(pack2(c1a.x, c1a.y), pack2(c2a.x, c2a.y));
        ull cp1 = add2(pack2(c1b.x, c1b.y), pack2(c2b.x, c2b.y));

        float ev = (lane < DE) ? ef[(size_t)e * DE + lane] : 0.f;

        #pragma unroll
        for (int k = 0; k < DE; ++k) {
            float ek = __shfl_sync(0xffffffffu, ev, k);
            ull ekk = pack2(ek, ek);
            gp0 = fma2(ekk, wg2[k][0], gp0);
            gp1 = fma2(ekk, wg2[k][1], gp1);
            cp0 = fma2(ekk, wc2[k][0], cp0);
            cp1 = fma2(ekk, wc2[k][1], cp1);
        }

        float gx, gy, gz, gw_;
        float cx, cy, cz, cw_;
        unpack2(gp0, gx, gy); unpack2(gp1, gz, gw_);
        unpack2(cp0, cx, cy); unpack2(cp1, cz, cw_);

        float4 m;
        m.x = sigmoid_f(gx)  * softplus_f(cx);
        m.y = sigmoid_f(gy)  * softplus_f(cy);
        m.z = sigmoid_f(gz)  * softplus_f(cz);
        m.w = sigmoid_f(gw_) * softplus_f(cw_);

        float* out = g_agg + (size_t)src * D + lane * 4;
        asm volatile("red.global.add.v4.f32 [%0], {%1,%2,%3,%4};"
                     :: "l"(out), "f"(m.x), "f"(m.y), "f"(m.z), "f"(m.w)
                     : "memory");
    }
}

// ---------------------------------------------------------------------------
// Kernel 4: BN stats (fp64 accumulate)
// ---------------------------------------------------------------------------
__global__ void stats_kernel() {
    int d = threadIdx.x;   // blockDim = 128
    double s = 0.0, s2 = 0.0;
    for (int n = blockIdx.x; n < N_NODES; n += gridDim.x) {
        float v = g_agg[(size_t)n * D + d];
        s  += (double)v;
        s2 += (double)v * (double)v;
    }
    atomicAdd(&g_sum[d], s);
    atomicAdd(&g_sumsq[d], s2);
}

// ---------------------------------------------------------------------------
// Kernel 5: fold BN stats into per-channel affine (a, b)
// ---------------------------------------------------------------------------
__global__ void stats_final(const float* __restrict__ gamma,
                            const float* __restrict__ beta) {
    int d = threadIdx.x;   // 128 threads, 1 block
    double mean = g_sum[d] * (1.0 / N_NODES);
    double var  = g_sumsq[d] * (1.0 / N_NODES) - mean * mean;
    float invstd = rsqrtf((float)var + BN_EPS);
    float a = invstd * gamma[d];
    g_a[d] = a;
    g_b[d] = beta[d] - (float)mean * a;
}

// ---------------------------------------------------------------------------
// Kernel 6: BN apply + residual + softplus
// ---------------------------------------------------------------------------
__global__ void final_kernel(const float* __restrict__ h,
                             float* __restrict__ out) {
    const int total4 = N_NODES * D / 4;
    for (int f4 = blockIdx.x * blockDim.x + threadIdx.x; f4 < total4;
         f4 += gridDim.x * blockDim.x) {
        int d4 = (f4 & 31) * 4;
        float4 av = ((const float4*)g_agg)[f4];
        float4 hv = ((const float4*)h)[f4];
        float4 aa = *(const float4*)&g_a[d4];
        float4 bb = *(const float4*)&g_b[d4];
        float4 r;
        r.x = softplus_f(hv.x + av.x * aa.x + bb.x);
        r.y = softplus_f(hv.y + av.y * aa.y + bb.y);
        r.z = softplus_f(hv.z + av.z * aa.z + bb.z);
        r.w = softplus_f(hv.w + av.w * aa.w + bb.w);
        ((float4*)out)[f4] = r;
    }
}

// ---------------------------------------------------------------------------
extern "C" void kernel_launch(void* const* d_in, const int* in_sizes, int n_in,
                              void* d_out, int out_size) {
    const float* h     = (const float*)d_in[0];
    const void*  ei    = d_in[1];
    const float* ef    = (const float*)d_in[2];
    const float* gw    = (const float*)d_in[3];
    const float* gb    = (const float*)d_in[4];
    const float* cw    = (const float*)d_in[5];
    const float* cb    = (const float*)d_in[6];
    const float* gamma = (const float*)d_in[7];
    const float* beta  = (const float*)d_in[8];
    float* out = (float*)d_out;

    detect_kernel<<<1, 32>>>((const int*)ei);
    zero_kernel<<<1024, 256>>>();
    dim3 gg((N_NODES + 63) / 64, 4);
    node_gemm<<<gg, 256>>>(h, gw, cw, gb, cb);
    edge_kernel<<<4096, 128>>>(ei, ef, gw, cw);
    stats_kernel<<<2048, 128>>>();
    stats_final<<<1, 128>>>(gamma, beta);
    final_kernel<<<1024, 256>>>(h, out);
}

// round 5
// speedup vs baseline: 8.1589x; 1.3314x over previous
#include <cuda_runtime.h>
#include <cuda_fp16.h>
#include <math.h>

#define N_NODES 50000
#define N_EDGES 800000
#define D       128
#define DE      10
#define BN_EPS  1e-5f

typedef unsigned long long ull;

// Scratch (device globals: allocation-free)
// P16 layout per node (512 halves): [0:128) g1=h@gw[0:128]+gb,
// [128:256) c1=h@cw[0:128]+cb, [256:384) g2=h@gw[128:256], [384:512) c2
__device__ __half  g_P16[N_NODES * 512];
__device__ float   g_agg[N_NODES * D];
__device__ double  g_sum[D];
__device__ double  g_sumsq[D];
__device__ float   g_a[D];
__device__ float   g_b[D];
__device__ int     g_is64;

// ---- packed f32x2 helpers (Blackwell FFMA2 path, PTX-only) ----
__device__ __forceinline__ ull pack2(float lo, float hi) {
    ull r; asm("mov.b64 %0, {%1, %2};" : "=l"(r) : "f"(lo), "f"(hi)); return r;
}
__device__ __forceinline__ void unpack2(ull v, float& lo, float& hi) {
    asm("mov.b64 {%0, %1}, %2;" : "=f"(lo), "=f"(hi) : "l"(v));
}
__device__ __forceinline__ ull fma2(ull a, ull b, ull c) {
    ull d; asm("fma.rn.f32x2 %0, %1, %2, %3;" : "=l"(d) : "l"(a), "l"(b), "l"(c));
    return d;
}
__device__ __forceinline__ ull add2(ull a, ull b) {
    ull d; asm("add.rn.f32x2 %0, %1, %2;" : "=l"(d) : "l"(a), "l"(b));
    return d;
}

__device__ __forceinline__ float softplus_f(float x) {
    return fmaxf(x, 0.0f) + __logf(1.0f + __expf(-fabsf(x)));
}
__device__ __forceinline__ float sigmoid_f(float x) {
    return 1.0f / (1.0f + __expf(-x));
}

// ---------------------------------------------------------------------------
// Kernel 0: detect edge_index dtype (int64 little-endian -> odd words all 0)
// ---------------------------------------------------------------------------
__global__ void detect_kernel(const int* __restrict__ ei32) {
    if (threadIdx.x == 0 && blockIdx.x == 0) {
        int nz = 0;
        #pragma unroll
        for (int i = 0; i < 64; ++i) nz |= ei32[2 * i + 1];
        g_is64 = (nz == 0) ? 1 : 0;
    }
}

// ---------------------------------------------------------------------------
// Kernel 1: zero agg + stat accumulators
// ---------------------------------------------------------------------------
__global__ void zero_kernel() {
    int idx = blockIdx.x * blockDim.x + threadIdx.x;
    const int total4 = N_NODES * D / 4;
    float4 z = make_float4(0.f, 0.f, 0.f, 0.f);
    for (int i = idx; i < total4; i += gridDim.x * blockDim.x)
        ((float4*)g_agg)[i] = z;
    if (blockIdx.x == 0 && threadIdx.x < D) {
        g_sum[threadIdx.x] = 0.0;
        g_sumsq[threadIdx.x] = 0.0;
    }
}

// ---------------------------------------------------------------------------
// Kernel 2: node projection GEMM (fp32 compute via f32x2, fp16 store).
// ---------------------------------------------------------------------------
__global__ __launch_bounds__(256) void node_gemm(
    const float* __restrict__ h,
    const float* __restrict__ gw, const float* __restrict__ cw,
    const float* __restrict__ gb, const float* __restrict__ cb)
{
    __shared__ float Hs[16][72];
    __shared__ float Ws[16][128];

    const int q    = blockIdx.y;
    const float* W = (q & 1) ? cw : gw;
    const int koff = (q >> 1) * 128;
    const int row0 = blockIdx.x * 64;
    const int tid  = threadIdx.x;
    const int tx   = tid & 31, ty = tid >> 5;

    ull acc2[4][4];
    #pragma unroll
    for (int p = 0; p < 4; ++p)
        #pragma unroll
        for (int c = 0; c < 4; ++c) acc2[p][c] = 0ull;

    for (int kc = 0; kc < 128; kc += 16) {
        {
            int r = tid >> 2, c4 = (tid & 3) * 4;
            float4 v = make_float4(0.f, 0.f, 0.f, 0.f);
            if (row0 + r < N_NODES)
                v = *(const float4*)&h[(size_t)(row0 + r) * 128 + kc + c4];
            Hs[c4 + 0][r] = v.x; Hs[c4 + 1][r] = v.y;
            Hs[c4 + 2][r] = v.z; Hs[c4 + 3][r] = v.w;
        }
        #pragma unroll
        for (int j = 0; j < 2; ++j) {
            int f4 = tid + j * 256;
            int kk = f4 >> 5, c4 = (f4 & 31) * 4;
            *(float4*)&Ws[kk][c4] =
                *(const float4*)&W[(size_t)(koff + kc + kk) * 128 + c4];
        }
        __syncthreads();

        #pragma unroll
        for (int kk = 0; kk < 16; ++kk) {
            float4 wv = *(float4*)&Ws[kk][tx * 4];
            float4 h0 = *(float4*)&Hs[kk][ty * 8];
            float4 h1 = *(float4*)&Hs[kk][ty * 8 + 4];
            ull wd[4] = {pack2(wv.x, wv.x), pack2(wv.y, wv.y),
                         pack2(wv.z, wv.z), pack2(wv.w, wv.w)};
            ull hp[4] = {pack2(h0.x, h0.y), pack2(h0.z, h0.w),
                         pack2(h1.x, h1.y), pack2(h1.z, h1.w)};
            #pragma unroll
            for (int p = 0; p < 4; ++p)
                #pragma unroll
                for (int c = 0; c < 4; ++c)
                    acc2[p][c] = fma2(hp[p], wd[c], acc2[p][c]);
        }
        __syncthreads();
    }

    float4 bv = make_float4(0.f, 0.f, 0.f, 0.f);
    if (q == 0)      bv = *(const float4*)&gb[tx * 4];
    else if (q == 1) bv = *(const float4*)&cb[tx * 4];

    #pragma unroll
    for (int p = 0; p < 4; ++p) {
        float v0[4], v1[4];
        #pragma unroll
        for (int c = 0; c < 4; ++c) unpack2(acc2[p][c], v0[c], v1[c]);
        #pragma unroll
        for (int s = 0; s < 2; ++s) {
            int r = row0 + ty * 8 + 2 * p + s;
            if (r < N_NODES) {
                float* v = s ? v1 : v0;
                __half2 a = __floats2half2_rn(v[0] + bv.x, v[1] + bv.y);
                __half2 b = __floats2half2_rn(v[2] + bv.z, v[3] + bv.w);
                uint2 st = make_uint2(*(unsigned*)&a, *(unsigned*)&b);
                *(uint2*)&g_P16[(size_t)r * 512 + q * 128 + tx * 4] = st;
            }
        }
    }
}

// ---------------------------------------------------------------------------
// Kernel 3: edge stage — W3 in SHARED (frees ~80 regs -> high occupancy),
// 2 edges per warp iteration (shared W3 LDS amortized, 12 gathers in flight).
// ---------------------------------------------------------------------------
__global__ __launch_bounds__(256) void edge_kernel(
    const void*  __restrict__ ei,
    const float* __restrict__ ef,
    const float* __restrict__ gw, const float* __restrict__ cw)
{
    __shared__ ull s_wg[DE][64];   // packed pairs: [k][p] = (w[2p], w[2p+1])
    __shared__ ull s_wc[DE][64];

    const int tid    = threadIdx.x;
    const int lane   = tid & 31;
    const int warp   = (blockIdx.x * blockDim.x + tid) >> 5;
    const int nwarps = (gridDim.x * blockDim.x) >> 5;
    const int is64   = g_is64;

    for (int i = tid; i < DE * 64; i += blockDim.x) {
        int k = i >> 6, p = i & 63;
        float2 g = *(const float2*)&gw[(size_t)(256 + k) * 128 + 2 * p];
        float2 c = *(const float2*)&cw[(size_t)(256 + k) * 128 + 2 * p];
        s_wg[k][p] = pack2(g.x, g.y);
        s_wc[k][p] = pack2(c.x, c.y);
    }
    __syncthreads();

    const int p0 = lane * 2, p1 = lane * 2 + 1;

    // N_EDGES is even and the stride is even, so e+1 is always valid.
    for (int e = warp * 2; e < N_EDGES; e += nwarps * 2) {
        int s0, d0, s1, d1;
        if (is64) {
            const long long* E = (const long long*)ei;
            s0 = (int)E[e];     d0 = (int)E[N_EDGES + e];
            s1 = (int)E[e + 1]; d1 = (int)E[N_EDGES + e + 1];
        } else {
            const int* E = (const int*)ei;
            s0 = E[e];     d0 = E[N_EDGES + e];
            s1 = E[e + 1]; d1 = E[N_EDGES + e + 1];
        }
        const __half* ps0 = g_P16 + (size_t)s0 * 512;
        const __half* pd0 = g_P16 + (size_t)d0 * 512;
        const __half* ps1 = g_P16 + (size_t)s1 * 512;
        const __half* pd1 = g_P16 + (size_t)d1 * 512;

        // 8 independent 8-byte gathers (max MLP)
        uint2 g10 = *(const uint2*)(ps0 + lane * 4);
        uint2 c10 = *(const uint2*)(ps0 + 128 + lane * 4);
        uint2 g20 = *(const uint2*)(pd0 + 256 + lane * 4);
        uint2 c20 = *(const uint2*)(pd0 + 384 + lane * 4);
        uint2 g11 = *(const uint2*)(ps1 + lane * 4);
        uint2 c11 = *(const uint2*)(ps1 + 128 + lane * 4);
        uint2 g21 = *(const uint2*)(pd1 + 256 + lane * 4);
        uint2 c21 = *(const uint2*)(pd1 + 384 + lane * 4);

        float ev0 = (lane < DE) ? ef[(size_t)e * DE + lane] : 0.f;
        float ev1 = (lane < DE) ? ef[(size_t)(e + 1) * DE + lane] : 0.f;

        #define H2F2(u) __half22float2(*(__half2*)&(u))
        float2 t0, t1;
        t0 = H2F2(g10.x); t1 = H2F2(g20.x);
        ull gp00 = add2(pack2(t0.x, t0.y), pack2(t1.x, t1.y));
        t0 = H2F2(g10.y); t1 = H2F2(g20.y);
        ull gp01 = add2(pack2(t0.x, t0.y), pack2(t1.x, t1.y));
        t0 = H2F2(c10.x); t1 = H2F2(c20.x);
        ull cp00 = add2(pack2(t0.x, t0.y), pack2(t1.x, t1.y));
        t0 = H2F2(c10.y); t1 = H2F2(c20.y);
        ull cp01 = add2(pack2(t0.x, t0.y), pack2(t1.x, t1.y));
        t0 = H2F2(g11.x); t1 = H2F2(g21.x);
        ull gp10 = add2(pack2(t0.x, t0.y), pack2(t1.x, t1.y));
        t0 = H2F2(g11.y); t1 = H2F2(g21.y);
        ull gp11 = add2(pack2(t0.x, t0.y), pack2(t1.x, t1.y));
        t0 = H2F2(c11.x); t1 = H2F2(c21.x);
        ull cp10 = add2(pack2(t0.x, t0.y), pack2(t1.x, t1.y));
        t0 = H2F2(c11.y); t1 = H2F2(c21.y);
        ull cp11 = add2(pack2(t0.x, t0.y), pack2(t1.x, t1.y));
        #undef H2F2

        #pragma unroll
        for (int k = 0; k < DE; ++k) {
            float ek0 = __shfl_sync(0xffffffffu, ev0, k);
            float ek1 = __shfl_sync(0xffffffffu, ev1, k);
            ull wgA = s_wg[k][p0], wgB = s_wg[k][p1];
            ull wcA = s_wc[k][p0], wcB = s_wc[k][p1];
            ull e0p = pack2(ek0, ek0);
            ull e1p = pack2(ek1, ek1);
            gp00 = fma2(e0p, wgA, gp00);
            gp01 = fma2(e0p, wgB, gp01);
            cp00 = fma2(e0p, wcA, cp00);
            cp01 = fma2(e0p, wcB, cp01);
            gp10 = fma2(e1p, wgA, gp10);
            gp11 = fma2(e1p, wgB, gp11);
            cp10 = fma2(e1p, wcA, cp10);
            cp11 = fma2(e1p, wcB, cp11);
        }

        float ga, gb_, gc, gd, ca, cb_, cc, cd;
        unpack2(gp00, ga, gb_); unpack2(gp01, gc, gd);
        unpack2(cp00, ca, cb_); unpack2(cp01, cc, cd);
        float4 m0;
        m0.x = sigmoid_f(ga)  * softplus_f(ca);
        m0.y = sigmoid_f(gb_) * softplus_f(cb_);
        m0.z = sigmoid_f(gc)  * softplus_f(cc);
        m0.w = sigmoid_f(gd)  * softplus_f(cd);
        float* o0 = g_agg + (size_t)s0 * D + lane * 4;
        asm volatile("red.global.add.v4.f32 [%0], {%1,%2,%3,%4};"
                     :: "l"(o0), "f"(m0.x), "f"(m0.y), "f"(m0.z), "f"(m0.w)
                     : "memory");

        unpack2(gp10, ga, gb_); unpack2(gp11, gc, gd);
        unpack2(cp10, ca, cb_); unpack2(cp11, cc, cd);
        float4 m1;
        m1.x = sigmoid_f(ga)  * softplus_f(ca);
        m1.y = sigmoid_f(gb_) * softplus_f(cb_);
        m1.z = sigmoid_f(gc)  * softplus_f(cc);
        m1.w = sigmoid_f(gd)  * softplus_f(cd);
        float* o1 = g_agg + (size_t)s1 * D + lane * 4;
        asm volatile("red.global.add.v4.f32 [%0], {%1,%2,%3,%4};"
                     :: "l"(o1), "f"(m1.x), "f"(m1.y), "f"(m1.z), "f"(m1.w)
                     : "memory");
    }
}

// ---------------------------------------------------------------------------
// Kernel 4: BN stats (fp64 accumulate)
// ---------------------------------------------------------------------------
__global__ void stats_kernel() {
    int d = threadIdx.x;   // blockDim = 128
    double s = 0.0, s2 = 0.0;
    for (int n = blockIdx.x; n < N_NODES; n += gridDim.x) {
        float v = g_agg[(size_t)n * D + d];
        s  += (double)v;
        s2 += (double)v * (double)v;
    }
    atomicAdd(&g_sum[d], s);
    atomicAdd(&g_sumsq[d], s2);
}

// ---------------------------------------------------------------------------
// Kernel 5: fold BN stats into per-channel affine (a, b)
// ---------------------------------------------------------------------------
__global__ void stats_final(const float* __restrict__ gamma,
                            const float* __restrict__ beta) {
    int d = threadIdx.x;
    double mean = g_sum[d] * (1.0 / N_NODES);
    double var  = g_sumsq[d] * (1.0 / N_NODES) - mean * mean;
    float invstd = rsqrtf((float)var + BN_EPS);
    float a = invstd * gamma[d];
    g_a[d] = a;
    g_b[d] = beta[d] - (float)mean * a;
}

// ---------------------------------------------------------------------------
// Kernel 6: BN apply + residual + softplus
// ---------------------------------------------------------------------------
__global__ void final_kernel(const float* __restrict__ h,
                             float* __restrict__ out) {
    const int total4 = N_NODES * D / 4;
    for (int f4 = blockIdx.x * blockDim.x + threadIdx.x; f4 < total4;
         f4 += gridDim.x * blockDim.x) {
        int d4 = (f4 & 31) * 4;
        float4 av = ((const float4*)g_agg)[f4];
        float4 hv = ((const float4*)h)[f4];
        float4 aa = *(const float4*)&g_a[d4];
        float4 bb = *(const float4*)&g_b[d4];
        float4 r;
        r.x = softplus_f(hv.x + av.x * aa.x + bb.x);
        r.y = softplus_f(hv.y + av.y * aa.y + bb.y);
        r.z = softplus_f(hv.z + av.z * aa.z + bb.z);
        r.w = softplus_f(hv.w + av.w * aa.w + bb.w);
        ((float4*)out)[f4] = r;
    }
}

// ---------------------------------------------------------------------------
extern "C" void kernel_launch(void* const* d_in, const int* in_sizes, int n_in,
                              void* d_out, int out_size) {
    const float* h     = (const float*)d_in[0];
    const void*  ei    = d_in[1];
    const float* ef    = (const float*)d_in[2];
    const float* gw    = (const float*)d_in[3];
    const float* gb    = (const float*)d_in[4];
    const float* cw    = (const float*)d_in[5];
    const float* cb    = (const float*)d_in[6];
    const float* gamma = (const float*)d_in[7];
    const float* beta  = (const float*)d_in[8];
    float* out = (float*)d_out;

    detect_kernel<<<1, 32>>>((const int*)ei);
    zero_kernel<<<1024, 256>>>();
    dim3 gg((N_NODES + 63) / 64, 4);
    node_gemm<<<gg, 256>>>(h, gw, cw, gb, cb);
    edge_kernel<<<2048, 256>>>(ei, ef, gw, cw);
    stats_kernel<<<2048, 128>>>();
    stats_final<<<1, 128>>>(gamma, beta);
    final_kernel<<<1024, 256>>>(h, out);
}

// round 6
// speedup vs baseline: 9.5408x; 1.1694x over previous
#include <cuda_runtime.h>
#include <cuda_fp16.h>
#include <math.h>

#define N_NODES 50000
#define N_EDGES 800000
#define D       128
#define DE      10
#define BN_EPS  1e-5f

typedef unsigned long long ull;

// Scratch (device globals: allocation-free)
// P16 layout per node (512 halves): [0:128) g1=h@gw[0:128]+gb,
// [128:256) c1=h@cw[0:128]+cb, [256:384) g2=h@gw[128:256], [384:512) c2
__device__ __half  g_P16[N_NODES * 512];
__device__ float   g_agg[N_NODES * D];
__device__ double  g_sum[D];
__device__ double  g_sumsq[D];
__device__ float   g_a[D];
__device__ float   g_b[D];
__device__ int     g_is64;

// ---- packed f32x2 helpers (Blackwell FFMA2 path, PTX-only) ----
__device__ __forceinline__ ull pack2(float lo, float hi) {
    ull r; asm("mov.b64 %0, {%1, %2};" : "=l"(r) : "f"(lo), "f"(hi)); return r;
}
__device__ __forceinline__ void unpack2(ull v, float& lo, float& hi) {
    asm("mov.b64 {%0, %1}, %2;" : "=f"(lo), "=f"(hi) : "l"(v));
}
__device__ __forceinline__ ull fma2(ull a, ull b, ull c) {
    ull d; asm("fma.rn.f32x2 %0, %1, %2, %3;" : "=l"(d) : "l"(a), "l"(b), "l"(c));
    return d;
}
__device__ __forceinline__ ull add2(ull a, ull b) {
    ull d; asm("add.rn.f32x2 %0, %1, %2;" : "=l"(d) : "l"(a), "l"(b));
    return d;
}

__device__ __forceinline__ float softplus_f(float x) {
    return fmaxf(x, 0.0f) + __logf(1.0f + __expf(-fabsf(x)));
}
__device__ __forceinline__ float sigmoid_f(float x) {
    return 1.0f / (1.0f + __expf(-x));
}

// ---------------------------------------------------------------------------
// Kernel 0: detect edge_index dtype (int64 little-endian -> odd words all 0)
// ---------------------------------------------------------------------------
__global__ void detect_kernel(const int* __restrict__ ei32) {
    if (threadIdx.x == 0 && blockIdx.x == 0) {
        int nz = 0;
        #pragma unroll
        for (int i = 0; i < 64; ++i) nz |= ei32[2 * i + 1];
        g_is64 = (nz == 0) ? 1 : 0;
    }
}

// ---------------------------------------------------------------------------
// Kernel 1: zero agg + stat accumulators
// ---------------------------------------------------------------------------
__global__ void zero_kernel() {
    int idx = blockIdx.x * blockDim.x + threadIdx.x;
    const int total4 = N_NODES * D / 4;
    float4 z = make_float4(0.f, 0.f, 0.f, 0.f);
    for (int i = idx; i < total4; i += gridDim.x * blockDim.x)
        ((float4*)g_agg)[i] = z;
    if (blockIdx.x == 0 && threadIdx.x < D) {
        g_sum[threadIdx.x] = 0.0;
        g_sumsq[threadIdx.x] = 0.0;
    }
}

// ---------------------------------------------------------------------------
// Kernel 2: node projection GEMM (fp32 compute via f32x2, fp16 store).
// ---------------------------------------------------------------------------
__global__ __launch_bounds__(256) void node_gemm(
    const float* __restrict__ h,
    const float* __restrict__ gw, const float* __restrict__ cw,
    const float* __restrict__ gb, const float* __restrict__ cb)
{
    __shared__ float Hs[16][72];
    __shared__ float Ws[16][128];

    const int q    = blockIdx.y;
    const float* W = (q & 1) ? cw : gw;
    const int koff = (q >> 1) * 128;
    const int row0 = blockIdx.x * 64;
    const int tid  = threadIdx.x;
    const int tx   = tid & 31, ty = tid >> 5;

    ull acc2[4][4];
    #pragma unroll
    for (int p = 0; p < 4; ++p)
        #pragma unroll
        for (int c = 0; c < 4; ++c) acc2[p][c] = 0ull;

    for (int kc = 0; kc < 128; kc += 16) {
        {
            int r = tid >> 2, c4 = (tid & 3) * 4;
            float4 v = make_float4(0.f, 0.f, 0.f, 0.f);
            if (row0 + r < N_NODES)
                v = *(const float4*)&h[(size_t)(row0 + r) * 128 + kc + c4];
            Hs[c4 + 0][r] = v.x; Hs[c4 + 1][r] = v.y;
            Hs[c4 + 2][r] = v.z; Hs[c4 + 3][r] = v.w;
        }
        #pragma unroll
        for (int j = 0; j < 2; ++j) {
            int f4 = tid + j * 256;
            int kk = f4 >> 5, c4 = (f4 & 31) * 4;
            *(float4*)&Ws[kk][c4] =
                *(const float4*)&W[(size_t)(koff + kc + kk) * 128 + c4];
        }
        __syncthreads();

        #pragma unroll
        for (int kk = 0; kk < 16; ++kk) {
            float4 wv = *(float4*)&Ws[kk][tx * 4];
            float4 h0 = *(float4*)&Hs[kk][ty * 8];
            float4 h1 = *(float4*)&Hs[kk][ty * 8 + 4];
            ull wd[4] = {pack2(wv.x, wv.x), pack2(wv.y, wv.y),
                         pack2(wv.z, wv.z), pack2(wv.w, wv.w)};
            ull hp[4] = {pack2(h0.x, h0.y), pack2(h0.z, h0.w),
                         pack2(h1.x, h1.y), pack2(h1.z, h1.w)};
            #pragma unroll
            for (int p = 0; p < 4; ++p)
                #pragma unroll
                for (int c = 0; c < 4; ++c)
                    acc2[p][c] = fma2(hp[p], wd[c], acc2[p][c]);
        }
        __syncthreads();
    }

    float4 bv = make_float4(0.f, 0.f, 0.f, 0.f);
    if (q == 0)      bv = *(const float4*)&gb[tx * 4];
    else if (q == 1) bv = *(const float4*)&cb[tx * 4];

    #pragma unroll
    for (int p = 0; p < 4; ++p) {
        float v0[4], v1[4];
        #pragma unroll
        for (int c = 0; c < 4; ++c) unpack2(acc2[p][c], v0[c], v1[c]);
        #pragma unroll
        for (int s = 0; s < 2; ++s) {
            int r = row0 + ty * 8 + 2 * p + s;
            if (r < N_NODES) {
                float* v = s ? v1 : v0;
                __half2 a = __floats2half2_rn(v[0] + bv.x, v[1] + bv.y);
                __half2 b = __floats2half2_rn(v[2] + bv.z, v[3] + bv.w);
                uint2 st = make_uint2(*(unsigned*)&a, *(unsigned*)&b);
                *(uint2*)&g_P16[(size_t)r * 512 + q * 128 + tx * 4] = st;
            }
        }
    }
}

// ---------------------------------------------------------------------------
// Kernel 3: edge stage — 4 edges per warp iteration. W3 in shared, read as
// 16B LDS.128 pairs and amortized over 4 edges (smem bytes/edge cut 4x vs R5).
// 16 independent gathers in flight per iteration.
// ---------------------------------------------------------------------------
__global__ __launch_bounds__(128) void edge_kernel(
    const void*  __restrict__ ei,
    const float* __restrict__ ef,
    const float* __restrict__ gw, const float* __restrict__ cw)
{
    __shared__ ull s_wg[DE][64];   // [k][p] = packed (w[2p], w[2p+1])
    __shared__ ull s_wc[DE][64];

    const int tid    = threadIdx.x;
    const int lane   = tid & 31;
    const int warp   = (blockIdx.x * blockDim.x + tid) >> 5;
    const int nwarps = (gridDim.x * blockDim.x) >> 5;
    const int is64   = g_is64;

    for (int i = tid; i < DE * 64; i += blockDim.x) {
        int k = i >> 6, p = i & 63;
        float2 g = *(const float2*)&gw[(size_t)(256 + k) * 128 + 2 * p];
        float2 c = *(const float2*)&cw[(size_t)(256 + k) * 128 + 2 * p];
        s_wg[k][p] = pack2(g.x, g.y);
        s_wc[k][p] = pack2(c.x, c.y);
    }
    __syncthreads();

    // N_EDGES % 4 == 0 and strides are multiples of 4: e..e+3 always valid.
    for (int e = warp * 4; e < N_EDGES; e += nwarps * 4) {
        int s[4], d[4];
        if (is64) {
            const long long* E = (const long long*)ei;
            #pragma unroll
            for (int j = 0; j < 4; ++j) {
                s[j] = (int)E[e + j];
                d[j] = (int)E[N_EDGES + e + j];
            }
        } else {
            const int* E = (const int*)ei;
            #pragma unroll
            for (int j = 0; j < 4; ++j) {
                s[j] = E[e + j];
                d[j] = E[N_EDGES + e + j];
            }
        }

        // 16 independent 8-byte gathers
        uint2 G1[4], C1[4], G2[4], C2[4];
        #pragma unroll
        for (int j = 0; j < 4; ++j) {
            const __half* ps = g_P16 + (size_t)s[j] * 512;
            const __half* pd = g_P16 + (size_t)d[j] * 512;
            G1[j] = *(const uint2*)(ps + lane * 4);
            C1[j] = *(const uint2*)(ps + 128 + lane * 4);
            G2[j] = *(const uint2*)(pd + 256 + lane * 4);
            C2[j] = *(const uint2*)(pd + 384 + lane * 4);
        }

        float ev[4];
        #pragma unroll
        for (int j = 0; j < 4; ++j)
            ev[j] = (lane < DE) ? ef[(size_t)(e + j) * DE + lane] : 0.f;

        // convert fp16 pairs -> packed f32x2 accumulators
        ull gp[4][2], cp[4][2];
        #define H2P(u) ({ float2 _t = __half22float2(*(__half2*)&(u)); \
                          pack2(_t.x, _t.y); })
        #pragma unroll
        for (int j = 0; j < 4; ++j) {
            gp[j][0] = add2(H2P(G1[j].x), H2P(G2[j].x));
            gp[j][1] = add2(H2P(G1[j].y), H2P(G2[j].y));
            cp[j][0] = add2(H2P(C1[j].x), H2P(C2[j].x));
            cp[j][1] = add2(H2P(C1[j].y), H2P(C2[j].y));
        }
        #undef H2P

        // rank-10 edge-feature update; W3 LDS amortized over 4 edges
        #pragma unroll
        for (int k = 0; k < DE; ++k) {
            ulonglong2 wg = *(const ulonglong2*)&s_wg[k][2 * lane];
            ulonglong2 wc = *(const ulonglong2*)&s_wc[k][2 * lane];
            #pragma unroll
            for (int j = 0; j < 4; ++j) {
                float ek = __shfl_sync(0xffffffffu, ev[j], k);
                ull ekk = pack2(ek, ek);
                gp[j][0] = fma2(ekk, wg.x, gp[j][0]);
                gp[j][1] = fma2(ekk, wg.y, gp[j][1]);
                cp[j][0] = fma2(ekk, wc.x, cp[j][0]);
                cp[j][1] = fma2(ekk, wc.y, cp[j][1]);
            }
        }

        // activations + scatter
        #pragma unroll
        for (int j = 0; j < 4; ++j) {
            float ga, gb_, gc, gd, ca, cb_, cc, cd;
            unpack2(gp[j][0], ga, gb_); unpack2(gp[j][1], gc, gd);
            unpack2(cp[j][0], ca, cb_); unpack2(cp[j][1], cc, cd);
            float4 m;
            m.x = sigmoid_f(ga)  * softplus_f(ca);
            m.y = sigmoid_f(gb_) * softplus_f(cb_);
            m.z = sigmoid_f(gc)  * softplus_f(cc);
            m.w = sigmoid_f(gd)  * softplus_f(cd);
            float* o = g_agg + (size_t)s[j] * D + lane * 4;
            asm volatile("red.global.add.v4.f32 [%0], {%1,%2,%3,%4};"
                         :: "l"(o), "f"(m.x), "f"(m.y), "f"(m.z), "f"(m.w)
                         : "memory");
        }
    }
}

// ---------------------------------------------------------------------------
// Kernel 4: BN stats (fp64 accumulate)
// ---------------------------------------------------------------------------
__global__ void stats_kernel() {
    int d = threadIdx.x;   // blockDim = 128
    double s = 0.0, s2 = 0.0;
    for (int n = blockIdx.x; n < N_NODES; n += gridDim.x) {
        float v = g_agg[(size_t)n * D + d];
        s  += (double)v;
        s2 += (double)v * (double)v;
    }
    atomicAdd(&g_sum[d], s);
    atomicAdd(&g_sumsq[d], s2);
}

// ---------------------------------------------------------------------------
// Kernel 5: fold BN stats into per-channel affine (a, b)
// ---------------------------------------------------------------------------
__global__ void stats_final(const float* __restrict__ gamma,
                            const float* __restrict__ beta) {
    int d = threadIdx.x;
    double mean = g_sum[d] * (1.0 / N_NODES);
    double var  = g_sumsq[d] * (1.0 / N_NODES) - mean * mean;
    float invstd = rsqrtf((float)var + BN_EPS);
    float a = invstd * gamma[d];
    g_a[d] = a;
    g_b[d] = beta[d] - (float)mean * a;
}

// ---------------------------------------------------------------------------
// Kernel 6: BN apply + residual + softplus
// ---------------------------------------------------------------------------
__global__ void final_kernel(const float* __restrict__ h,
                             float* __restrict__ out) {
    const int total4 = N_NODES * D / 4;
    for (int f4 = blockIdx.x * blockDim.x + threadIdx.x; f4 < total4;
         f4 += gridDim.x * blockDim.x) {
        int d4 = (f4 & 31) * 4;
        float4 av = ((const float4*)g_agg)[f4];
        float4 hv = ((const float4*)h)[f4];
        float4 aa = *(const float4*)&g_a[d4];
        float4 bb = *(const float4*)&g_b[d4];
        float4 r;
        r.x = softplus_f(hv.x + av.x * aa.x + bb.x);
        r.y = softplus_f(hv.y + av.y * aa.y + bb.y);
        r.z = softplus_f(hv.z + av.z * aa.z + bb.z);
        r.w = softplus_f(hv.w + av.w * aa.w + bb.w);
        ((float4*)out)[f4] = r;
    }
}

// ---------------------------------------------------------------------------
extern "C" void kernel_launch(void* const* d_in, const int* in_sizes, int n_in,
                              void* d_out, int out_size) {
    const float* h     = (const float*)d_in[0];
    const void*  ei    = d_in[1];
    const float* ef    = (const float*)d_in[2];
    const float* gw    = (const float*)d_in[3];
    const float* gb    = (const float*)d_in[4];
    const float* cw    = (const float*)d_in[5];
    const float* cb    = (const float*)d_in[6];
    const float* gamma = (const float*)d_in[7];
    const float* beta  = (const float*)d_in[8];
    float* out = (float*)d_out;

    detect_kernel<<<1, 32>>>((const int*)ei);
    zero_kernel<<<1024, 256>>>();
    dim3 gg((N_NODES + 63) / 64, 4);
    node_gemm<<<gg, 256>>>(h, gw, cw, gb, cb);
    edge_kernel<<<4096, 128>>>(ei, ef, gw, cw);
    stats_kernel<<<2048, 128>>>();
    stats_final<<<1, 128>>>(gamma, beta);
    final_kernel<<<1024, 256>>>(h, out);
}

// round 7
// speedup vs baseline: 12.0067x; 1.2585x over previous
#include <cuda_runtime.h>
#include <cuda_fp16.h>
#include <math.h>

#define N_NODES 50000
#define N_EDGES 800000
#define D       128
#define DE      10
#define BN_EPS  1e-5f
#define M_TILES 3125          // 50000 / 16

typedef unsigned long long ull;

// Scratch (device globals: allocation-free)
// P16 layout per node (512 halves): [0:128) g1=h@gw[0:128]+gb,
// [128:256) c1=h@cw[0:128]+cb, [256:384) g2=h@gw[128:256], [384:512) c2
__device__ __half  g_P16[N_NODES * 512];
__device__ __half  g_h16[N_NODES * D];
__device__ __half  g_w16[4 * 128 * 128];   // [q][k][c]
__device__ float   g_agg[N_NODES * D];
__device__ double  g_sum[D];
__device__ double  g_sumsq[D];
__device__ float   g_a[D];
__device__ float   g_b[D];
__device__ int     g_is64;

// ---- packed f32x2 helpers (Blackwell FFMA2 path, PTX-only) ----
__device__ __forceinline__ ull pack2(float lo, float hi) {
    ull r; asm("mov.b64 %0, {%1, %2};" : "=l"(r) : "f"(lo), "f"(hi)); return r;
}
__device__ __forceinline__ void unpack2(ull v, float& lo, float& hi) {
    asm("mov.b64 {%0, %1}, %2;" : "=f"(lo), "=f"(hi) : "l"(v));
}
__device__ __forceinline__ ull fma2(ull a, ull b, ull c) {
    ull d; asm("fma.rn.f32x2 %0, %1, %2, %3;" : "=l"(d) : "l"(a), "l"(b), "l"(c));
    return d;
}
__device__ __forceinline__ ull add2(ull a, ull b) {
    ull d; asm("add.rn.f32x2 %0, %1, %2;" : "=l"(d) : "l"(a), "l"(b));
    return d;
}

__device__ __forceinline__ float softplus_f(float x) {
    return fmaxf(x, 0.0f) + __logf(1.0f + __expf(-fabsf(x)));
}
__device__ __forceinline__ float sigmoid_f(float x) {
    return 1.0f / (1.0f + __expf(-x));
}

// ---- mma / ldmatrix wrappers ----
__device__ __forceinline__ unsigned smem_u32(const void* p) {
    return (unsigned)__cvta_generic_to_shared(p);
}
__device__ __forceinline__ void ldsm_x4(unsigned& a0, unsigned& a1,
                                        unsigned& a2, unsigned& a3, unsigned addr) {
    asm volatile("ldmatrix.sync.aligned.m8n8.x4.shared.b16 {%0,%1,%2,%3}, [%4];"
                 : "=r"(a0), "=r"(a1), "=r"(a2), "=r"(a3) : "r"(addr));
}
__device__ __forceinline__ void ldsm_x2t(unsigned& b0, unsigned& b1, unsigned addr) {
    asm volatile("ldmatrix.sync.aligned.m8n8.x2.trans.shared.b16 {%0,%1}, [%2];"
                 : "=r"(b0), "=r"(b1) : "r"(addr));
}
__device__ __forceinline__ void mma16816(float* d, const unsigned* a, const unsigned* b) {
    asm volatile(
        "mma.sync.aligned.m16n8k16.row.col.f32.f16.f16.f32 "
        "{%0,%1,%2,%3}, {%4,%5,%6,%7}, {%8,%9}, {%0,%1,%2,%3};"
        : "+f"(d[0]), "+f"(d[1]), "+f"(d[2]), "+f"(d[3])
        : "r"(a[0]), "r"(a[1]), "r"(a[2]), "r"(a[3]), "r"(b[0]), "r"(b[1]));
}

// ---------------------------------------------------------------------------
// Kernel 0: detect edge_index dtype (int64 little-endian -> odd words all 0)
// ---------------------------------------------------------------------------
__global__ void detect_kernel(const int* __restrict__ ei32) {
    if (threadIdx.x == 0 && blockIdx.x == 0) {
        int nz = 0;
        #pragma unroll
        for (int i = 0; i < 64; ++i) nz |= ei32[2 * i + 1];
        g_is64 = (nz == 0) ? 1 : 0;
    }
}

// ---------------------------------------------------------------------------
// Kernel 1: zero agg + stat accumulators
// ---------------------------------------------------------------------------
__global__ void zero_kernel() {
    int idx = blockIdx.x * blockDim.x + threadIdx.x;
    const int total4 = N_NODES * D / 4;
    float4 z = make_float4(0.f, 0.f, 0.f, 0.f);
    for (int i = idx; i < total4; i += gridDim.x * blockDim.x)
        ((float4*)g_agg)[i] = z;
    if (blockIdx.x == 0 && threadIdx.x < D) {
        g_sum[threadIdx.x] = 0.0;
        g_sumsq[threadIdx.x] = 0.0;
    }
}

// ---------------------------------------------------------------------------
// Kernel 2a: convert h -> fp16
// ---------------------------------------------------------------------------
__global__ void convert_h(const float* __restrict__ h) {
    const int total4 = N_NODES * D / 4;
    for (int i = blockIdx.x * blockDim.x + threadIdx.x; i < total4;
         i += gridDim.x * blockDim.x) {
        float4 v = ((const float4*)h)[i];
        __half2 a = __floats2half2_rn(v.x, v.y);
        __half2 b = __floats2half2_rn(v.z, v.w);
        ((uint2*)g_h16)[i] = make_uint2(*(unsigned*)&a, *(unsigned*)&b);
    }
}

// ---------------------------------------------------------------------------
// Kernel 2b: convert W quadrants -> fp16  [q][k][c]
// q0: gw[k][c], q1: cw[k][c], q2: gw[128+k][c], q3: cw[128+k][c]
// ---------------------------------------------------------------------------
__global__ void convert_w(const float* __restrict__ gw,
                          const float* __restrict__ cw) {
    int i = blockIdx.x * blockDim.x + threadIdx.x;   // 65536 total
    if (i < 4 * 128 * 128) {
        int q = i >> 14, k = (i >> 7) & 127, c = i & 127;
        const float* W = (q & 1) ? cw : gw;
        g_w16[i] = __float2half(W[(size_t)((q >> 1) * 128 + k) * 128 + c]);
    }
}

// ---------------------------------------------------------------------------
// Kernel 2c: node projection GEMM on tensor cores (HMMA m16n8k16).
// Block 256 (8 warps). blockIdx.y = quadrant q. Warp w covers cols [16w,16w+16).
// B-fragments (W quadrant) cached in registers once; then stream 16-row
// M-tiles of h16 through shared with ldmatrix + mma.
// ---------------------------------------------------------------------------
__global__ __launch_bounds__(256) void node_gemm_tc(
    const float* __restrict__ gb, const float* __restrict__ cb)
{
    __shared__ __half S[128 * 136];   // W staging, then A tiles (rows 0-15)

    const int q    = blockIdx.y;
    const int tid  = threadIdx.x;
    const int w    = tid >> 5;
    const int lane = tid & 31;
    const unsigned sbase = smem_u32(S);

    // ---- stage W quadrant into shared (padded rows of 136 halves) ----
    const __half* wq = g_w16 + (size_t)q * 16384;
    #pragma unroll
    for (int j = 0; j < 8; ++j) {
        int i = tid + j * 256;             // 2048 uint4 total
        int row = i >> 4, colh = (i & 15) * 8;
        *(uint4*)&S[row * 136 + colh] = *(const uint4*)&wq[row * 128 + colh];
    }
    __syncthreads();

    // ---- extract B fragments: Bf[kstep][ntile][2] ----
    unsigned Bf[8][2][2];
    {
        int krow = lane & 15;
        #pragma unroll
        for (int ks = 0; ks < 8; ++ks)
            #pragma unroll
            for (int nt = 0; nt < 2; ++nt) {
                int cbase = w * 16 + nt * 8;
                unsigned addr = sbase +
                    ((unsigned)((ks * 16 + krow) * 136 + cbase) << 1);
                ldsm_x2t(Bf[ks][nt][0], Bf[ks][nt][1], addr);
            }
    }

    // ---- bias for this warp's columns (q<2 only) ----
    int ccol0 = w * 16 + (lane & 3) * 2;
    float bx0 = 0.f, by0 = 0.f, bx1 = 0.f, by1 = 0.f;
    if (q == 0) {
        bx0 = gb[ccol0];     by0 = gb[ccol0 + 1];
        bx1 = gb[ccol0 + 8]; by1 = gb[ccol0 + 9];
    } else if (q == 1) {
        bx0 = cb[ccol0];     by0 = cb[ccol0 + 1];
        bx1 = cb[ccol0 + 8]; by1 = cb[ccol0 + 9];
    }

    const int arow = lane & 15;
    const int acol = (lane >> 4) * 8;

    for (int mt = blockIdx.x; mt < M_TILES; mt += gridDim.x) {
        __syncthreads();   // protect shared A from previous iteration readers
        // stage 16 rows of h16 (1 uint4 per thread)
        {
            int row = tid >> 4, colh = (tid & 15) * 8;
            *(uint4*)&S[row * 136 + colh] =
                *(const uint4*)&g_h16[(size_t)(mt * 16 + row) * 128 + colh];
        }
        __syncthreads();

        float acc0[4] = {0.f, 0.f, 0.f, 0.f};
        float acc1[4] = {0.f, 0.f, 0.f, 0.f};
        #pragma unroll
        for (int ks = 0; ks < 8; ++ks) {
            unsigned a[4];
            unsigned addr = sbase +
                ((unsigned)(arow * 136 + ks * 16 + acol) << 1);
            ldsm_x4(a[0], a[1], a[2], a[3], addr);
            mma16816(acc0, a, Bf[ks][0]);
            mma16816(acc1, a, Bf[ks][1]);
        }

        // epilogue: bias + fp16 store to g_P16
        int r0 = mt * 16 + (lane >> 2);
        size_t base = (size_t)r0 * 512 + q * 128;
        __half2 v;
        v = __floats2half2_rn(acc0[0] + bx0, acc0[1] + by0);
        *(__half2*)&g_P16[base + ccol0] = v;
        v = __floats2half2_rn(acc1[0] + bx1, acc1[1] + by1);
        *(__half2*)&g_P16[base + ccol0 + 8] = v;
        base += 8 * 512;
        v = __floats2half2_rn(acc0[2] + bx0, acc0[3] + by0);
        *(__half2*)&g_P16[base + ccol0] = v;
        v = __floats2half2_rn(acc1[2] + bx1, acc1[3] + by1);
        *(__half2*)&g_P16[base + ccol0 + 8] = v;
    }
}

// ---------------------------------------------------------------------------
// Kernel 3: edge stage — 4 edges per warp iteration. W3 in shared (LDS.128,
// amortized over 4 edges), 16 gathers in flight, f32x2 math, red.v4 scatter.
// ---------------------------------------------------------------------------
__global__ __launch_bounds__(128) void edge_kernel(
    const void*  __restrict__ ei,
    const float* __restrict__ ef,
    const float* __restrict__ gw, const float* __restrict__ cw)
{
    __shared__ ull s_wg[DE][64];   // [k][p] = packed (w[2p], w[2p+1])
    __shared__ ull s_wc[DE][64];

    const int tid    = threadIdx.x;
    const int lane   = tid & 31;
    const int warp   = (blockIdx.x * blockDim.x + tid) >> 5;
    const int nwarps = (gridDim.x * blockDim.x) >> 5;
    const int is64   = g_is64;

    for (int i = tid; i < DE * 64; i += blockDim.x) {
        int k = i >> 6, p = i & 63;
        float2 g = *(const float2*)&gw[(size_t)(256 + k) * 128 + 2 * p];
        float2 c = *(const float2*)&cw[(size_t)(256 + k) * 128 + 2 * p];
        s_wg[k][p] = pack2(g.x, g.y);
        s_wc[k][p] = pack2(c.x, c.y);
    }
    __syncthreads();

    for (int e = warp * 4; e < N_EDGES; e += nwarps * 4) {
        int s[4], d[4];
        if (is64) {
            const long long* E = (const long long*)ei;
            #pragma unroll
            for (int j = 0; j < 4; ++j) {
                s[j] = (int)E[e + j];
                d[j] = (int)E[N_EDGES + e + j];
            }
        } else {
            const int* E = (const int*)ei;
            #pragma unroll
            for (int j = 0; j < 4; ++j) {
                s[j] = E[e + j];
                d[j] = E[N_EDGES + e + j];
            }
        }

        uint2 G1[4], C1[4], G2[4], C2[4];
        #pragma unroll
        for (int j = 0; j < 4; ++j) {
            const __half* ps = g_P16 + (size_t)s[j] * 512;
            const __half* pd = g_P16 + (size_t)d[j] * 512;
            G1[j] = *(const uint2*)(ps + lane * 4);
            C1[j] = *(const uint2*)(ps + 128 + lane * 4);
            G2[j] = *(const uint2*)(pd + 256 + lane * 4);
            C2[j] = *(const uint2*)(pd + 384 + lane * 4);
        }

        float ev[4];
        #pragma unroll
        for (int j = 0; j < 4; ++j)
            ev[j] = (lane < DE) ? ef[(size_t)(e + j) * DE + lane] : 0.f;

        ull gp[4][2], cp[4][2];
        #define H2P(u) ({ float2 _t = __half22float2(*(__half2*)&(u)); \
                          pack2(_t.x, _t.y); })
        #pragma unroll
        for (int j = 0; j < 4; ++j) {
            gp[j][0] = add2(H2P(G1[j].x), H2P(G2[j].x));
            gp[j][1] = add2(H2P(G1[j].y), H2P(G2[j].y));
            cp[j][0] = add2(H2P(C1[j].x), H2P(C2[j].x));
            cp[j][1] = add2(H2P(C1[j].y), H2P(C2[j].y));
        }
        #undef H2P

        #pragma unroll
        for (int k = 0; k < DE; ++k) {
            ulonglong2 wg = *(const ulonglong2*)&s_wg[k][2 * lane];
            ulonglong2 wc = *(const ulonglong2*)&s_wc[k][2 * lane];
            #pragma unroll
            for (int j = 0; j < 4; ++j) {
                float ek = __shfl_sync(0xffffffffu, ev[j], k);
                ull ekk = pack2(ek, ek);
                gp[j][0] = fma2(ekk, wg.x, gp[j][0]);
                gp[j][1] = fma2(ekk, wg.y, gp[j][1]);
                cp[j][0] = fma2(ekk, wc.x, cp[j][0]);
                cp[j][1] = fma2(ekk, wc.y, cp[j][1]);
            }
        }

        #pragma unroll
        for (int j = 0; j < 4; ++j) {
            float ga, gb_, gc, gd, ca, cb_, cc, cd;
            unpack2(gp[j][0], ga, gb_); unpack2(gp[j][1], gc, gd);
            unpack2(cp[j][0], ca, cb_); unpack2(cp[j][1], cc, cd);
            float4 m;
            m.x = sigmoid_f(ga)  * softplus_f(ca);
            m.y = sigmoid_f(gb_) * softplus_f(cb_);
            m.z = sigmoid_f(gc)  * softplus_f(cc);
            m.w = sigmoid_f(gd)  * softplus_f(cd);
            float* o = g_agg + (size_t)s[j] * D + lane * 4;
            asm volatile("red.global.add.v4.f32 [%0], {%1,%2,%3,%4};"
                         :: "l"(o), "f"(m.x), "f"(m.y), "f"(m.z), "f"(m.w)
                         : "memory");
        }
    }
}

// ---------------------------------------------------------------------------
// Kernel 4: BN stats (fp64 accumulate)
// ---------------------------------------------------------------------------
__global__ void stats_kernel() {
    int d = threadIdx.x;   // blockDim = 128
    double s = 0.0, s2 = 0.0;
    for (int n = blockIdx.x; n < N_NODES; n += gridDim.x) {
        float v = g_agg[(size_t)n * D + d];
        s  += (double)v;
        s2 += (double)v * (double)v;
    }
    atomicAdd(&g_sum[d], s);
    atomicAdd(&g_sumsq[d], s2);
}

// ---------------------------------------------------------------------------
// Kernel 5: fold BN stats into per-channel affine (a, b)
// ---------------------------------------------------------------------------
__global__ void stats_final(const float* __restrict__ gamma,
                            const float* __restrict__ beta) {
    int d = threadIdx.x;
    double mean = g_sum[d] * (1.0 / N_NODES);
    double var  = g_sumsq[d] * (1.0 / N_NODES) - mean * mean;
    float invstd = rsqrtf((float)var + BN_EPS);
    float a = invstd * gamma[d];
    g_a[d] = a;
    g_b[d] = beta[d] - (float)mean * a;
}

// ---------------------------------------------------------------------------
// Kernel 6: BN apply + residual + softplus
// ---------------------------------------------------------------------------
__global__ void final_kernel(const float* __restrict__ h,
                             float* __restrict__ out) {
    const int total4 = N_NODES * D / 4;
    for (int f4 = blockIdx.x * blockDim.x + threadIdx.x; f4 < total4;
         f4 += gridDim.x * blockDim.x) {
        int d4 = (f4 & 31) * 4;
        float4 av = ((const float4*)g_agg)[f4];
        float4 hv = ((const float4*)h)[f4];
        float4 aa = *(const float4*)&g_a[d4];
        float4 bb = *(const float4*)&g_b[d4];
        float4 r;
        r.x = softplus_f(hv.x + av.x * aa.x + bb.x);
        r.y = softplus_f(hv.y + av.y * aa.y + bb.y);
        r.z = softplus_f(hv.z + av.z * aa.z + bb.z);
        r.w = softplus_f(hv.w + av.w * aa.w + bb.w);
        ((float4*)out)[f4] = r;
    }
}

// ---------------------------------------------------------------------------
extern "C" void kernel_launch(void* const* d_in, const int* in_sizes, int n_in,
                              void* d_out, int out_size) {
    const float* h     = (const float*)d_in[0];
    const void*  ei    = d_in[1];
    const float* ef    = (const float*)d_in[2];
    const float* gw    = (const float*)d_in[3];
    const float* gb    = (const float*)d_in[4];
    const float* cw    = (const float*)d_in[5];
    const float* cb    = (const float*)d_in[6];
    const float* gamma = (const float*)d_in[7];
    const float* beta  = (const float*)d_in[8];
    float* out = (float*)d_out;

    detect_kernel<<<1, 32>>>((const int*)ei);
    zero_kernel<<<1024, 256>>>();
    convert_h<<<2048, 256>>>(h);
    convert_w<<<256, 256>>>(gw, cw);
    dim3 gg(782, 4);
    node_gemm_tc<<<gg, 256>>>(gb, cb);
    edge_kernel<<<4096, 128>>>(ei, ef, gw, cw);
    stats_kernel<<<2048, 128>>>();
    stats_final<<<1, 128>>>(gamma, beta);
    final_kernel<<<1024, 256>>>(h, out);
}

// round 8
// speedup vs baseline: 12.7023x; 1.0579x over previous
#include <cuda_runtime.h>
#include <cuda_fp16.h>
#include <math.h>

#define N_NODES 50000
#define N_EDGES 800000
#define D       128
#define DE      10
#define BN_EPS  1e-5f
#define M_TILES 3125          // 50000 / 16

typedef unsigned long long ull;

// Scratch (device globals: allocation-free)
// P16 layout per node (512 halves): [0:128) g1=h@gw[0:128]+gb,
// [128:256) c1=h@cw[0:128]+cb, [256:384) g2=h@gw[128:256], [384:512) c2
__device__ __half  g_P16[N_NODES * 512];
__device__ __half  g_h16[N_NODES * D];
__device__ __half  g_w16[4 * 128 * 128];   // [q][k][c]
__device__ float   g_agg[N_NODES * D];
__device__ double  g_sum[D];
__device__ double  g_sumsq[D];
__device__ float   g_a[D];
__device__ float   g_b[D];
__device__ int     g_is64;

__device__ __forceinline__ float softplus_f(float x) {
    return fmaxf(x, 0.0f) + __logf(1.0f + __expf(-fabsf(x)));
}
__device__ __forceinline__ float sigmoid_f(float x) {
    return 1.0f / (1.0f + __expf(-x));
}

// ---- mma / ldmatrix wrappers ----
__device__ __forceinline__ unsigned smem_u32(const void* p) {
    return (unsigned)__cvta_generic_to_shared(p);
}
__device__ __forceinline__ void ldsm_x4(unsigned& a0, unsigned& a1,
                                        unsigned& a2, unsigned& a3, unsigned addr) {
    asm volatile("ldmatrix.sync.aligned.m8n8.x4.shared.b16 {%0,%1,%2,%3}, [%4];"
                 : "=r"(a0), "=r"(a1), "=r"(a2), "=r"(a3) : "r"(addr));
}
__device__ __forceinline__ void ldsm_x2t(unsigned& b0, unsigned& b1, unsigned addr) {
    asm volatile("ldmatrix.sync.aligned.m8n8.x2.trans.shared.b16 {%0,%1}, [%2];"
                 : "=r"(b0), "=r"(b1) : "r"(addr));
}
__device__ __forceinline__ void mma16816(float* d, const unsigned* a, const unsigned* b) {
    asm volatile(
        "mma.sync.aligned.m16n8k16.row.col.f32.f16.f16.f32 "
        "{%0,%1,%2,%3}, {%4,%5,%6,%7}, {%8,%9}, {%0,%1,%2,%3};"
        : "+f"(d[0]), "+f"(d[1]), "+f"(d[2]), "+f"(d[3])
        : "r"(a[0]), "r"(a[1]), "r"(a[2]), "r"(a[3]), "r"(b[0]), "r"(b[1]));
}

// ---------------------------------------------------------------------------
// Kernel 1: zero agg + stat accumulators + convert h -> fp16 (fused)
// ---------------------------------------------------------------------------
__global__ void prep_kernel(const float* __restrict__ h) {
    const int total4 = N_NODES * D / 4;
    float4 z = make_float4(0.f, 0.f, 0.f, 0.f);
    for (int i = blockIdx.x * blockDim.x + threadIdx.x; i < total4;
         i += gridDim.x * blockDim.x) {
        ((float4*)g_agg)[i] = z;
        float4 v = ((const float4*)h)[i];
        __half2 a = __floats2half2_rn(v.x, v.y);
        __half2 b = __floats2half2_rn(v.z, v.w);
        ((uint2*)g_h16)[i] = make_uint2(*(unsigned*)&a, *(unsigned*)&b);
    }
    if (blockIdx.x == 0 && threadIdx.x < D) {
        g_sum[threadIdx.x] = 0.0;
        g_sumsq[threadIdx.x] = 0.0;
    }
}

// ---------------------------------------------------------------------------
// Kernel 2: convert W quadrants -> fp16 [q][k][c] + edge dtype detect
// ---------------------------------------------------------------------------
__global__ void convert_w(const float* __restrict__ gw,
                          const float* __restrict__ cw,
                          const int* __restrict__ ei32) {
    int i = blockIdx.x * blockDim.x + threadIdx.x;
    if (i < 4 * 128 * 128) {
        int q = i >> 14, k = (i >> 7) & 127, c = i & 127;
        const float* W = (q & 1) ? cw : gw;
        g_w16[i] = __float2half(W[(size_t)((q >> 1) * 128 + k) * 128 + c]);
    }
    if (i == 0) {
        int nz = 0;
        #pragma unroll
        for (int j = 0; j < 64; ++j) nz |= ei32[2 * j + 1];
        g_is64 = (nz == 0) ? 1 : 0;
    }
}

// ---------------------------------------------------------------------------
// Kernel 3: node projection GEMM on tensor cores (HMMA m16n8k16).
// ---------------------------------------------------------------------------
__global__ __launch_bounds__(256) void node_gemm_tc(
    const float* __restrict__ gb, const float* __restrict__ cb)
{
    __shared__ __half S[128 * 136];

    const int q    = blockIdx.y;
    const int tid  = threadIdx.x;
    const int w    = tid >> 5;
    const int lane = tid & 31;
    const unsigned sbase = smem_u32(S);

    const __half* wq = g_w16 + (size_t)q * 16384;
    #pragma unroll
    for (int j = 0; j < 8; ++j) {
        int i = tid + j * 256;
        int row = i >> 4, colh = (i & 15) * 8;
        *(uint4*)&S[row * 136 + colh] = *(const uint4*)&wq[row * 128 + colh];
    }
    __syncthreads();

    unsigned Bf[8][2][2];
    {
        int krow = lane & 15;
        #pragma unroll
        for (int ks = 0; ks < 8; ++ks)
            #pragma unroll
            for (int nt = 0; nt < 2; ++nt) {
                int cbase = w * 16 + nt * 8;
                unsigned addr = sbase +
                    ((unsigned)((ks * 16 + krow) * 136 + cbase) << 1);
                ldsm_x2t(Bf[ks][nt][0], Bf[ks][nt][1], addr);
            }
    }

    int ccol0 = w * 16 + (lane & 3) * 2;
    float bx0 = 0.f, by0 = 0.f, bx1 = 0.f, by1 = 0.f;
    if (q == 0) {
        bx0 = gb[ccol0];     by0 = gb[ccol0 + 1];
        bx1 = gb[ccol0 + 8]; by1 = gb[ccol0 + 9];
    } else if (q == 1) {
        bx0 = cb[ccol0];     by0 = cb[ccol0 + 1];
        bx1 = cb[ccol0 + 8]; by1 = cb[ccol0 + 9];
    }

    const int arow = lane & 15;
    const int acol = (lane >> 4) * 8;

    for (int mt = blockIdx.x; mt < M_TILES; mt += gridDim.x) {
        __syncthreads();
        {
            int row = tid >> 4, colh = (tid & 15) * 8;
            *(uint4*)&S[row * 136 + colh] =
                *(const uint4*)&g_h16[(size_t)(mt * 16 + row) * 128 + colh];
        }
        __syncthreads();

        float acc0[4] = {0.f, 0.f, 0.f, 0.f};
        float acc1[4] = {0.f, 0.f, 0.f, 0.f};
        #pragma unroll
        for (int ks = 0; ks < 8; ++ks) {
            unsigned a[4];
            unsigned addr = sbase +
                ((unsigned)(arow * 136 + ks * 16 + acol) << 1);
            ldsm_x4(a[0], a[1], a[2], a[3], addr);
            mma16816(acc0, a, Bf[ks][0]);
            mma16816(acc1, a, Bf[ks][1]);
        }

        int r0 = mt * 16 + (lane >> 2);
        size_t base = (size_t)r0 * 512 + q * 128;
        __half2 v;
        v = __floats2half2_rn(acc0[0] + bx0, acc0[1] + by0);
        *(__half2*)&g_P16[base + ccol0] = v;
        v = __floats2half2_rn(acc1[0] + bx1, acc1[1] + by1);
        *(__half2*)&g_P16[base + ccol0 + 8] = v;
        base += 8 * 512;
        v = __floats2half2_rn(acc0[2] + bx0, acc0[3] + by0);
        *(__half2*)&g_P16[base + ccol0] = v;
        v = __floats2half2_rn(acc1[2] + bx1, acc1[3] + by1);
        *(__half2*)&g_P16[base + ccol0 + 8] = v;
    }
}

// ---------------------------------------------------------------------------
// Kernel 4: edge stage — fp16 W3 in shared (ONE LDS.128/k/lane holds all 8
// weights), half2 accumulation (base + rank-10), half2 shfl broadcast,
// 4 edges/warp iteration, red.v4 scatter.
// ---------------------------------------------------------------------------
__global__ __launch_bounds__(256, 4) void edge_kernel(
    const void*  __restrict__ ei,
    const float* __restrict__ ef,
    const float* __restrict__ gw, const float* __restrict__ cw)
{
    // s_w[k][lane] = {g(d0,d1), g(d2,d3), c(d0,d1), c(d2,d3)} as half2s
    __shared__ uint4 s_w[DE][32];

    const int tid    = threadIdx.x;
    const int lane   = tid & 31;
    const int warp   = (blockIdx.x * blockDim.x + tid) >> 5;
    const int nwarps = (gridDim.x * blockDim.x) >> 5;
    const int is64   = g_is64;

    for (int i = tid; i < DE * 32; i += blockDim.x) {
        int k = i >> 5, p = i & 31;
        float4 g = *(const float4*)&gw[(size_t)(256 + k) * 128 + p * 4];
        float4 c = *(const float4*)&cw[(size_t)(256 + k) * 128 + p * 4];
        __half2 g0 = __floats2half2_rn(g.x, g.y);
        __half2 g1 = __floats2half2_rn(g.z, g.w);
        __half2 c0 = __floats2half2_rn(c.x, c.y);
        __half2 c1 = __floats2half2_rn(c.z, c.w);
        s_w[k][p] = make_uint4(*(unsigned*)&g0, *(unsigned*)&g1,
                               *(unsigned*)&c0, *(unsigned*)&c1);
    }
    __syncthreads();

    for (int e = warp * 4; e < N_EDGES; e += nwarps * 4) {
        int s[4], d[4];
        if (is64) {
            const long long* E = (const long long*)ei;
            #pragma unroll
            for (int j = 0; j < 4; ++j) {
                s[j] = (int)E[e + j];
                d[j] = (int)E[N_EDGES + e + j];
            }
        } else {
            const int* E = (const int*)ei;
            #pragma unroll
            for (int j = 0; j < 4; ++j) {
                s[j] = E[e + j];
                d[j] = E[N_EDGES + e + j];
            }
        }

        // 16 independent 8B gathers -> fp16 base sums (g1+g2, c1+c2)
        __half2 bg0[4], bg1[4], bc0[4], bc1[4];
        #pragma unroll
        for (int j = 0; j < 4; ++j) {
            const __half* ps = g_P16 + (size_t)s[j] * 512;
            const __half* pd = g_P16 + (size_t)d[j] * 512;
            uint2 G1 = *(const uint2*)(ps + lane * 4);
            uint2 C1 = *(const uint2*)(ps + 128 + lane * 4);
            uint2 G2 = *(const uint2*)(pd + 256 + lane * 4);
            uint2 C2 = *(const uint2*)(pd + 384 + lane * 4);
            bg0[j] = __hadd2(*(__half2*)&G1.x, *(__half2*)&G2.x);
            bg1[j] = __hadd2(*(__half2*)&G1.y, *(__half2*)&G2.y);
            bc0[j] = __hadd2(*(__half2*)&C1.x, *(__half2*)&C2.x);
            bc1[j] = __hadd2(*(__half2*)&C1.y, *(__half2*)&C2.y);
        }

        // edge features as replicated half2 for shfl broadcast
        unsigned evu[4];
        #pragma unroll
        for (int j = 0; j < 4; ++j) {
            float ev = (lane < DE) ? ef[(size_t)(e + j) * DE + lane] : 0.f;
            __half2 t = __floats2half2_rn(ev, ev);
            evu[j] = *(unsigned*)&t;
        }

        // rank-10 update in half2; W3 LDS.128 amortized over 4 edges
        __half2 rg0[4] = {}, rg1[4] = {}, rc0[4] = {}, rc1[4] = {};
        #pragma unroll
        for (int k = 0; k < DE; ++k) {
            uint4 wv = s_w[k][lane];
            __half2 wG0 = *(__half2*)&wv.x, wG1 = *(__half2*)&wv.y;
            __half2 wC0 = *(__half2*)&wv.z, wC1 = *(__half2*)&wv.w;
            #pragma unroll
            for (int j = 0; j < 4; ++j) {
                unsigned eku = __shfl_sync(0xffffffffu, evu[j], k);
                __half2 ek2 = *(__half2*)&eku;
                rg0[j] = __hfma2(ek2, wG0, rg0[j]);
                rg1[j] = __hfma2(ek2, wG1, rg1[j]);
                rc0[j] = __hfma2(ek2, wC0, rc0[j]);
                rc1[j] = __hfma2(ek2, wC1, rc1[j]);
            }
        }

        // combine, activations (f32), scatter
        #pragma unroll
        for (int j = 0; j < 4; ++j) {
            float2 gA = __half22float2(__hadd2(bg0[j], rg0[j]));
            float2 gB = __half22float2(__hadd2(bg1[j], rg1[j]));
            float2 cA = __half22float2(__hadd2(bc0[j], rc0[j]));
            float2 cB = __half22float2(__hadd2(bc1[j], rc1[j]));
            float4 m;
            m.x = sigmoid_f(gA.x) * softplus_f(cA.x);
            m.y = sigmoid_f(gA.y) * softplus_f(cA.y);
            m.z = sigmoid_f(gB.x) * softplus_f(cB.x);
            m.w = sigmoid_f(gB.y) * softplus_f(cB.y);
            float* o = g_agg + (size_t)s[j] * D + lane * 4;
            asm volatile("red.global.add.v4.f32 [%0], {%1,%2,%3,%4};"
                         :: "l"(o), "f"(m.x), "f"(m.y), "f"(m.z), "f"(m.w)
                         : "memory");
        }
    }
}

// ---------------------------------------------------------------------------
// Kernel 5: BN stats (fp64 accumulate)
// ---------------------------------------------------------------------------
__global__ void stats_kernel() {
    int d = threadIdx.x;   // blockDim = 128
    double s = 0.0, s2 = 0.0;
    for (int n = blockIdx.x; n < N_NODES; n += gridDim.x) {
        float v = g_agg[(size_t)n * D + d];
        s  += (double)v;
        s2 += (double)v * (double)v;
    }
    atomicAdd(&g_sum[d], s);
    atomicAdd(&g_sumsq[d], s2);
}

// ---------------------------------------------------------------------------
// Kernel 6: fold BN stats into per-channel affine (a, b)
// ---------------------------------------------------------------------------
__global__ void stats_final(const float* __restrict__ gamma,
                            const float* __restrict__ beta) {
    int d = threadIdx.x;
    double mean = g_sum[d] * (1.0 / N_NODES);
    double var  = g_sumsq[d] * (1.0 / N_NODES) - mean * mean;
    float invstd = rsqrtf((float)var + BN_EPS);
    float a = invstd * gamma[d];
    g_a[d] = a;
    g_b[d] = beta[d] - (float)mean * a;
}

// ---------------------------------------------------------------------------
// Kernel 7: BN apply + residual + softplus
// ---------------------------------------------------------------------------
__global__ void final_kernel(const float* __restrict__ h,
                             float* __restrict__ out) {
    const int total4 = N_NODES * D / 4;
    for (int f4 = blockIdx.x * blockDim.x + threadIdx.x; f4 < total4;
         f4 += gridDim.x * blockDim.x) {
        int d4 = (f4 & 31) * 4;
        float4 av = ((const float4*)g_agg)[f4];
        float4 hv = ((const float4*)h)[f4];
        float4 aa = *(const float4*)&g_a[d4];
        float4 bb = *(const float4*)&g_b[d4];
        float4 r;
        r.x = softplus_f(hv.x + av.x * aa.x + bb.x);
        r.y = softplus_f(hv.y + av.y * aa.y + bb.y);
        r.z = softplus_f(hv.z + av.z * aa.z + bb.z);
        r.w = softplus_f(hv.w + av.w * aa.w + bb.w);
        ((float4*)out)[f4] = r;
    }
}

// ---------------------------------------------------------------------------
extern "C" void kernel_launch(void* const* d_in, const int* in_sizes, int n_in,
                              void* d_out, int out_size) {
    const float* h     = (const float*)d_in[0];
    const void*  ei    = d_in[1];
    const float* ef    = (const float*)d_in[2];
    const float* gw    = (const float*)d_in[3];
    const float* gb    = (const float*)d_in[4];
    const float* cw    = (const float*)d_in[5];
    const float* cb    = (const float*)d_in[6];
    const float* gamma = (const float*)d_in[7];
    const float* beta  = (const float*)d_in[8];
    float* out = (float*)d_out;

    prep_kernel<<<1024, 256>>>(h);
    convert_w<<<256, 256>>>(gw, cw, (const int*)ei);
    dim3 gg(782, 4);
    node_gemm_tc<<<gg, 256>>>(gb, cb);
    edge_kernel<<<2048, 256>>>(ei, ef, gw, cw);
    stats_kernel<<<2048, 128>>>();
    stats_final<<<1, 128>>>(gamma, beta);
    final_kernel<<<1024, 256>>>(h, out);
}

// round 9
// speedup vs baseline: 13.5789x; 1.0690x over previous
#include <cuda_runtime.h>
#include <cuda_fp16.h>
#include <math.h>

#define N_NODES 50000
#define N_EDGES 800000
#define D       128
#define DE      10
#define BN_EPS  1e-5f
#define M_TILES 3125          // 50000 / 16

typedef unsigned long long ull;

// Scratch (device globals: allocation-free)
// P16 layout per node (512 halves): [0:128) g1=h@gw[0:128]+gb,
// [128:256) c1=h@cw[0:128]+cb, [256:384) g2=h@gw[128:256], [384:512) c2
__device__ __half  g_P16[N_NODES * 512];
__device__ __half  g_h16[N_NODES * D];
__device__ __half  g_w16[4 * 128 * 128];   // [q][k][c]
__device__ float   g_agg[N_NODES * D];
__device__ double  g_sum[D];
__device__ double  g_sumsq[D];
__device__ int     g_is64;

__device__ __forceinline__ float softplus_f(float x) {
    return fmaxf(x, 0.0f) + __logf(1.0f + __expf(-fabsf(x)));
}
__device__ __forceinline__ float sigmoid_f(float x) {
    return 1.0f / (1.0f + __expf(-x));
}

// ---- mma / ldmatrix wrappers ----
__device__ __forceinline__ unsigned smem_u32(const void* p) {
    return (unsigned)__cvta_generic_to_shared(p);
}
__device__ __forceinline__ void ldsm_x4(unsigned& a0, unsigned& a1,
                                        unsigned& a2, unsigned& a3, unsigned addr) {
    asm volatile("ldmatrix.sync.aligned.m8n8.x4.shared.b16 {%0,%1,%2,%3}, [%4];"
                 : "=r"(a0), "=r"(a1), "=r"(a2), "=r"(a3) : "r"(addr));
}
__device__ __forceinline__ void ldsm_x2t(unsigned& b0, unsigned& b1, unsigned addr) {
    asm volatile("ldmatrix.sync.aligned.m8n8.x2.trans.shared.b16 {%0,%1}, [%2];"
                 : "=r"(b0), "=r"(b1) : "r"(addr));
}
__device__ __forceinline__ void mma16816(float* d, const unsigned* a, const unsigned* b) {
    asm volatile(
        "mma.sync.aligned.m16n8k16.row.col.f32.f16.f16.f32 "
        "{%0,%1,%2,%3}, {%4,%5,%6,%7}, {%8,%9}, {%0,%1,%2,%3};"
        : "+f"(d[0]), "+f"(d[1]), "+f"(d[2]), "+f"(d[3])
        : "r"(a[0]), "r"(a[1]), "r"(a[2]), "r"(a[3]), "r"(b[0]), "r"(b[1]));
}

// ---------------------------------------------------------------------------
// Kernel 1: zero agg + stat accumulators + convert h -> fp16 (fused)
// ---------------------------------------------------------------------------
__global__ void prep_kernel(const float* __restrict__ h) {
    const int total4 = N_NODES * D / 4;
    float4 z = make_float4(0.f, 0.f, 0.f, 0.f);
    for (int i = blockIdx.x * blockDim.x + threadIdx.x; i < total4;
         i += gridDim.x * blockDim.x) {
        ((float4*)g_agg)[i] = z;
        float4 v = ((const float4*)h)[i];
        __half2 a = __floats2half2_rn(v.x, v.y);
        __half2 b = __floats2half2_rn(v.z, v.w);
        ((uint2*)g_h16)[i] = make_uint2(*(unsigned*)&a, *(unsigned*)&b);
    }
    if (blockIdx.x == 0 && threadIdx.x < D) {
        g_sum[threadIdx.x] = 0.0;
        g_sumsq[threadIdx.x] = 0.0;
    }
}

// ---------------------------------------------------------------------------
// Kernel 2: convert W quadrants -> fp16 [q][k][c] + edge dtype detect
// ---------------------------------------------------------------------------
__global__ void convert_w(const float* __restrict__ gw,
                          const float* __restrict__ cw,
                          const int* __restrict__ ei32) {
    int i = blockIdx.x * blockDim.x + threadIdx.x;
    if (i < 4 * 128 * 128) {
        int q = i >> 14, k = (i >> 7) & 127, c = i & 127;
        const float* W = (q & 1) ? cw : gw;
        g_w16[i] = __float2half(W[(size_t)((q >> 1) * 128 + k) * 128 + c]);
    }
    if (i == 0) {
        int nz = 0;
        #pragma unroll
        for (int j = 0; j < 64; ++j) nz |= ei32[2 * j + 1];
        g_is64 = (nz == 0) ? 1 : 0;
    }
}

// ---------------------------------------------------------------------------
// Kernel 3: node projection GEMM on tensor cores (HMMA m16n8k16).
// ---------------------------------------------------------------------------
__global__ __launch_bounds__(256) void node_gemm_tc(
    const float* __restrict__ gb, const float* __restrict__ cb)
{
    __shared__ __half S[128 * 136];

    const int q    = blockIdx.y;
    const int tid  = threadIdx.x;
    const int w    = tid >> 5;
    const int lane = tid & 31;
    const unsigned sbase = smem_u32(S);

    const __half* wq = g_w16 + (size_t)q * 16384;
    #pragma unroll
    for (int j = 0; j < 8; ++j) {
        int i = tid + j * 256;
        int row = i >> 4, colh = (i & 15) * 8;
        *(uint4*)&S[row * 136 + colh] = *(const uint4*)&wq[row * 128 + colh];
    }
    __syncthreads();

    unsigned Bf[8][2][2];
    {
        int krow = lane & 15;
        #pragma unroll
        for (int ks = 0; ks < 8; ++ks)
            #pragma unroll
            for (int nt = 0; nt < 2; ++nt) {
                int cbase = w * 16 + nt * 8;
                unsigned addr = sbase +
                    ((unsigned)((ks * 16 + krow) * 136 + cbase) << 1);
                ldsm_x2t(Bf[ks][nt][0], Bf[ks][nt][1], addr);
            }
    }

    int ccol0 = w * 16 + (lane & 3) * 2;
    float bx0 = 0.f, by0 = 0.f, bx1 = 0.f, by1 = 0.f;
    if (q == 0) {
        bx0 = gb[ccol0];     by0 = gb[ccol0 + 1];
        bx1 = gb[ccol0 + 8]; by1 = gb[ccol0 + 9];
    } else if (q == 1) {
        bx0 = cb[ccol0];     by0 = cb[ccol0 + 1];
        bx1 = cb[ccol0 + 8]; by1 = cb[ccol0 + 9];
    }

    const int arow = lane & 15;
    const int acol = (lane >> 4) * 8;

    for (int mt = blockIdx.x; mt < M_TILES; mt += gridDim.x) {
        __syncthreads();
        {
            int row = tid >> 4, colh = (tid & 15) * 8;
            *(uint4*)&S[row * 136 + colh] =
                *(const uint4*)&g_h16[(size_t)(mt * 16 + row) * 128 + colh];
        }
        __syncthreads();

        float acc0[4] = {0.f, 0.f, 0.f, 0.f};
        float acc1[4] = {0.f, 0.f, 0.f, 0.f};
        #pragma unroll
        for (int ks = 0; ks < 8; ++ks) {
            unsigned a[4];
            unsigned addr = sbase +
                ((unsigned)(arow * 136 + ks * 16 + acol) << 1);
            ldsm_x4(a[0], a[1], a[2], a[3], addr);
            mma16816(acc0, a, Bf[ks][0]);
            mma16816(acc1, a, Bf[ks][1]);
        }

        int r0 = mt * 16 + (lane >> 2);
        size_t base = (size_t)r0 * 512 + q * 128;
        __half2 v;
        v = __floats2half2_rn(acc0[0] + bx0, acc0[1] + by0);
        *(__half2*)&g_P16[base + ccol0] = v;
        v = __floats2half2_rn(acc1[0] + bx1, acc1[1] + by1);
        *(__half2*)&g_P16[base + ccol0 + 8] = v;
        base += 8 * 512;
        v = __floats2half2_rn(acc0[2] + bx0, acc0[3] + by0);
        *(__half2*)&g_P16[base + ccol0] = v;
        v = __floats2half2_rn(acc1[2] + bx1, acc1[3] + by1);
        *(__half2*)&g_P16[base + ccol0 + 8] = v;
    }
}

// ---------------------------------------------------------------------------
// Kernel 4: edge stage — fp16 W3 in shared (ONE LDS.128/k/lane, amortized over
// 4 edges), half2 accumulators INITIALIZED from gathered base sums (saves the
// final combine and 16 regs), high occupancy: 128 thr x 10 CTAs (51-reg cap).
// ---------------------------------------------------------------------------
__global__ __launch_bounds__(128, 10) void edge_kernel(
    const void*  __restrict__ ei,
    const float* __restrict__ ef,
    const float* __restrict__ gw, const float* __restrict__ cw)
{
    // s_w[k][lane] = {g(d0,d1), g(d2,d3), c(d0,d1), c(d2,d3)} as half2s
    __shared__ uint4 s_w[DE][32];

    const int tid    = threadIdx.x;
    const int lane   = tid & 31;
    const int warp   = (blockIdx.x * blockDim.x + tid) >> 5;
    const int nwarps = (gridDim.x * blockDim.x) >> 5;
    const int is64   = g_is64;

    for (int i = tid; i < DE * 32; i += blockDim.x) {
        int k = i >> 5, p = i & 31;
        float4 g = *(const float4*)&gw[(size_t)(256 + k) * 128 + p * 4];
        float4 c = *(const float4*)&cw[(size_t)(256 + k) * 128 + p * 4];
        __half2 g0 = __floats2half2_rn(g.x, g.y);
        __half2 g1 = __floats2half2_rn(g.z, g.w);
        __half2 c0 = __floats2half2_rn(c.x, c.y);
        __half2 c1 = __floats2half2_rn(c.z, c.w);
        s_w[k][p] = make_uint4(*(unsigned*)&g0, *(unsigned*)&g1,
                               *(unsigned*)&c0, *(unsigned*)&c1);
    }
    __syncthreads();

    for (int e = warp * 4; e < N_EDGES; e += nwarps * 4) {
        int s[4], d[4];
        if (is64) {
            const long long* E = (const long long*)ei;
            #pragma unroll
            for (int j = 0; j < 4; ++j) {
                s[j] = (int)E[e + j];
                d[j] = (int)E[N_EDGES + e + j];
            }
        } else {
            const int* E = (const int*)ei;
            #pragma unroll
            for (int j = 0; j < 4; ++j) {
                s[j] = E[e + j];
                d[j] = E[N_EDGES + e + j];
            }
        }

        // 16 independent 8B gathers; accumulators init = g1+g2 / c1+c2
        __half2 rg0[4], rg1[4], rc0[4], rc1[4];
        #pragma unroll
        for (int j = 0; j < 4; ++j) {
            const __half* ps = g_P16 + (size_t)s[j] * 512;
            const __half* pd = g_P16 + (size_t)d[j] * 512;
            uint2 G1 = *(const uint2*)(ps + lane * 4);
            uint2 C1 = *(const uint2*)(ps + 128 + lane * 4);
            uint2 G2 = *(const uint2*)(pd + 256 + lane * 4);
            uint2 C2 = *(const uint2*)(pd + 384 + lane * 4);
            rg0[j] = __hadd2(*(__half2*)&G1.x, *(__half2*)&G2.x);
            rg1[j] = __hadd2(*(__half2*)&G1.y, *(__half2*)&G2.y);
            rc0[j] = __hadd2(*(__half2*)&C1.x, *(__half2*)&C2.x);
            rc1[j] = __hadd2(*(__half2*)&C1.y, *(__half2*)&C2.y);
        }

        // edge features as replicated half2 for shfl broadcast
        unsigned evu[4];
        #pragma unroll
        for (int j = 0; j < 4; ++j) {
            float ev = (lane < DE) ? ef[(size_t)(e + j) * DE + lane] : 0.f;
            __half2 t = __floats2half2_rn(ev, ev);
            evu[j] = *(unsigned*)&t;
        }

        // rank-10 update in half2; W3 LDS.128 amortized over 4 edges
        #pragma unroll
        for (int k = 0; k < DE; ++k) {
            uint4 wv = s_w[k][lane];
            __half2 wG0 = *(__half2*)&wv.x, wG1 = *(__half2*)&wv.y;
            __half2 wC0 = *(__half2*)&wv.z, wC1 = *(__half2*)&wv.w;
            #pragma unroll
            for (int j = 0; j < 4; ++j) {
                unsigned eku = __shfl_sync(0xffffffffu, evu[j], k);
                __half2 ek2 = *(__half2*)&eku;
                rg0[j] = __hfma2(ek2, wG0, rg0[j]);
                rg1[j] = __hfma2(ek2, wG1, rg1[j]);
                rc0[j] = __hfma2(ek2, wC0, rc0[j]);
                rc1[j] = __hfma2(ek2, wC1, rc1[j]);
            }
        }

        // activations (f32) + scatter
        #pragma unroll
        for (int j = 0; j < 4; ++j) {
            float2 gA = __half22float2(rg0[j]);
            float2 gB = __half22float2(rg1[j]);
            float2 cA = __half22float2(rc0[j]);
            float2 cB = __half22float2(rc1[j]);
            float4 m;
            m.x = sigmoid_f(gA.x) * softplus_f(cA.x);
            m.y = sigmoid_f(gA.y) * softplus_f(cA.y);
            m.z = sigmoid_f(gB.x) * softplus_f(cB.x);
            m.w = sigmoid_f(gB.y) * softplus_f(cB.y);
            float* o = g_agg + (size_t)s[j] * D + lane * 4;
            asm volatile("red.global.add.v4.f32 [%0], {%1,%2,%3,%4};"
                         :: "l"(o), "f"(m.x), "f"(m.y), "f"(m.z), "f"(m.w)
                         : "memory");
        }
    }
}

// ---------------------------------------------------------------------------
// Kernel 5: BN stats (fp64 accumulate)
// ---------------------------------------------------------------------------
__global__ void stats_kernel() {
    int d = threadIdx.x;   // blockDim = 128
    double s = 0.0, s2 = 0.0;
    for (int n = blockIdx.x; n < N_NODES; n += gridDim.x) {
        float v = g_agg[(size_t)n * D + d];
        s  += (double)v;
        s2 += (double)v * (double)v;
    }
    atomicAdd(&g_sum[d], s);
    atomicAdd(&g_sumsq[d], s2);
}

// ---------------------------------------------------------------------------
// Kernel 6: BN affine fold (per-block, in smem) + apply + residual + softplus
// ---------------------------------------------------------------------------
__global__ __launch_bounds__(256) void final_kernel(
    const float* __restrict__ h,
    const float* __restrict__ gamma, const float* __restrict__ beta,
    float* __restrict__ out)
{
    __shared__ float sa[D], sb[D];
    if (threadIdx.x < D) {
        int d = threadIdx.x;
        double mean = g_sum[d] * (1.0 / N_NODES);
        double var  = g_sumsq[d] * (1.0 / N_NODES) - mean * mean;
        float invstd = rsqrtf((float)var + BN_EPS);
        float a = invstd * gamma[d];
        sa[d] = a;
        sb[d] = beta[d] - (float)mean * a;
    }
    __syncthreads();

    const int total4 = N_NODES * D / 4;
    for (int f4 = blockIdx.x * blockDim.x + threadIdx.x; f4 < total4;
         f4 += gridDim.x * blockDim.x) {
        int d4 = (f4 & 31) * 4;
        float4 av = ((const float4*)g_agg)[f4];
        float4 hv = ((const float4*)h)[f4];
        float4 aa = *(const float4*)&sa[d4];
        float4 bb = *(const float4*)&sb[d4];
        float4 r;
        r.x = softplus_f(hv.x + av.x * aa.x + bb.x);
        r.y = softplus_f(hv.y + av.y * aa.y + bb.y);
        r.z = softplus_f(hv.z + av.z * aa.z + bb.z);
        r.w = softplus_f(hv.w + av.w * aa.w + bb.w);
        ((float4*)out)[f4] = r;
    }
}

// ---------------------------------------------------------------------------
extern "C" void kernel_launch(void* const* d_in, const int* in_sizes, int n_in,
                              void* d_out, int out_size) {
    const float* h     = (const float*)d_in[0];
    const void*  ei    = d_in[1];
    const float* ef    = (const float*)d_in[2];
    const float* gw    = (const float*)d_in[3];
    const float* gb    = (const float*)d_in[4];
    const float* cw    = (const float*)d_in[5];
    const float* cb    = (const float*)d_in[6];
    const float* gamma = (const float*)d_in[7];
    const float* beta  = (const float*)d_in[8];
    float* out = (float*)d_out;

    prep_kernel<<<1024, 256>>>(h);
    convert_w<<<256, 256>>>(gw, cw, (const int*)ei);
    dim3 gg(782, 4);
    node_gemm_tc<<<gg, 256>>>(gb, cb);
    edge_kernel<<<4096, 128>>>(ei, ef, gw, cw);
    stats_kernel<<<2048, 128>>>();
    final_kernel<<<1024, 256>>>(h, gamma, beta, out);
}

// round 10
// speedup vs baseline: 15.1608x; 1.1165x over previous
#include <cuda_runtime.h>
#include <cuda_fp16.h>
#include <math.h>

#define N_NODES 50000
#define N_EDGES 800000
#define D       128
#define DE      10
#define BN_EPS  1e-5f
#define M_TILES 3125          // 50000 / 16

typedef unsigned long long ull;

// Scratch (device globals: allocation-free)
// P16 per node: 512 halves in two 256-half blocks.
//   src block [0:256):  granule l (l=0..31) = {g1[4l..4l+3], c1[4l..4l+3]}
//   dst block [256:512): granule l = {g2[4l..4l+3], c2[4l..4l+3]}
// (g1 = h@gw[0:128]+gb, c1 = h@cw[0:128]+cb, g2 = h@gw[128:256], c2 = ...)
__device__ __half  g_P16[N_NODES * 512];
__device__ __half  g_h16[N_NODES * D];
__device__ __half  g_w16[4 * 128 * 128];   // [q][k][c]
__device__ float   g_agg[N_NODES * D];
__device__ double  g_sum[D];
__device__ double  g_sumsq[D];
__device__ int     g_is64;

__device__ __forceinline__ float softplus_f(float x) {
    return fmaxf(x, 0.0f) + __logf(1.0f + __expf(-fabsf(x)));
}
__device__ __forceinline__ float sigmoid_f(float x) {
    // 1 MUFU via tanh.approx (vs ex2 + fp32 division)
    float y;
    asm("tanh.approx.f32 %0, %1;" : "=f"(y) : "f"(0.5f * x));
    return fmaf(0.5f, y, 0.5f);
}

// ---- mma / ldmatrix wrappers ----
__device__ __forceinline__ unsigned smem_u32(const void* p) {
    return (unsigned)__cvta_generic_to_shared(p);
}
__device__ __forceinline__ void ldsm_x4(unsigned& a0, unsigned& a1,
                                        unsigned& a2, unsigned& a3, unsigned addr) {
    asm volatile("ldmatrix.sync.aligned.m8n8.x4.shared.b16 {%0,%1,%2,%3}, [%4];"
                 : "=r"(a0), "=r"(a1), "=r"(a2), "=r"(a3) : "r"(addr));
}
__device__ __forceinline__ void ldsm_x2t(unsigned& b0, unsigned& b1, unsigned addr) {
    asm volatile("ldmatrix.sync.aligned.m8n8.x2.trans.shared.b16 {%0,%1}, [%2];"
                 : "=r"(b0), "=r"(b1) : "r"(addr));
}
__device__ __forceinline__ void mma16816(float* d, const unsigned* a, const unsigned* b) {
    asm volatile(
        "mma.sync.aligned.m16n8k16.row.col.f32.f16.f16.f32 "
        "{%0,%1,%2,%3}, {%4,%5,%6,%7}, {%8,%9}, {%0,%1,%2,%3};"
        : "+f"(d[0]), "+f"(d[1]), "+f"(d[2]), "+f"(d[3])
        : "r"(a[0]), "r"(a[1]), "r"(a[2]), "r"(a[3]), "r"(b[0]), "r"(b[1]));
}

// P16 offset for logical (quadrant q, channel d) within a node's 512 halves
__device__ __host__ __forceinline__ int p16_off(int q, int d) {
    return ((q >> 1) ? 256 : 0) + (d >> 2) * 8 + ((q & 1) ? 4 : 0) + (d & 3);
}

// ---------------------------------------------------------------------------
// Kernel 1: zero agg + stats + convert h -> fp16 + convert W -> fp16 + detect
// ---------------------------------------------------------------------------
__global__ void prep_kernel(const float* __restrict__ h,
                            const float* __restrict__ gw,
                            const float* __restrict__ cw,
                            const int* __restrict__ ei32) {
    const int total4 = N_NODES * D / 4;
    float4 z = make_float4(0.f, 0.f, 0.f, 0.f);
    int gid = blockIdx.x * blockDim.x + threadIdx.x;
    for (int i = gid; i < total4; i += gridDim.x * blockDim.x) {
        ((float4*)g_agg)[i] = z;
        float4 v = ((const float4*)h)[i];
        __half2 a = __floats2half2_rn(v.x, v.y);
        __half2 b = __floats2half2_rn(v.z, v.w);
        ((uint2*)g_h16)[i] = make_uint2(*(unsigned*)&a, *(unsigned*)&b);
    }
    if (gid < 4 * 128 * 128 / 2) {   // 2 elements each
        int i = gid * 2;
        int q = i >> 14, k = (i >> 7) & 127, c = i & 127;
        const float* W = (q & 1) ? cw : gw;
        float2 wv = *(const float2*)&W[(size_t)((q >> 1) * 128 + k) * 128 + c];
        *(__half2*)&g_w16[i] = __floats2half2_rn(wv.x, wv.y);
    }
    if (gid == 0) {
        int nz = 0;
        #pragma unroll
        for (int j = 0; j < 64; ++j) nz |= ei32[2 * j + 1];
        g_is64 = (nz == 0) ? 1 : 0;
    }
    if (blockIdx.x == 0 && threadIdx.x < D) {
        g_sum[threadIdx.x] = 0.0;
        g_sumsq[threadIdx.x] = 0.0;
    }
}

// ---------------------------------------------------------------------------
// Kernel 2: node projection GEMM on tensor cores (HMMA m16n8k16).
// Epilogue stores into the interleaved P16 layout via p16_off().
// ---------------------------------------------------------------------------
__global__ __launch_bounds__(256) void node_gemm_tc(
    const float* __restrict__ gb, const float* __restrict__ cb)
{
    __shared__ __half S[128 * 136];

    const int q    = blockIdx.y;
    const int tid  = threadIdx.x;
    const int w    = tid >> 5;
    const int lane = tid & 31;
    const unsigned sbase = smem_u32(S);

    const __half* wq = g_w16 + (size_t)q * 16384;
    #pragma unroll
    for (int j = 0; j < 8; ++j) {
        int i = tid + j * 256;
        int row = i >> 4, colh = (i & 15) * 8;
        *(uint4*)&S[row * 136 + colh] = *(const uint4*)&wq[row * 128 + colh];
    }
    __syncthreads();

    unsigned Bf[8][2][2];
    {
        int krow = lane & 15;
        #pragma unroll
        for (int ks = 0; ks < 8; ++ks)
            #pragma unroll
            for (int nt = 0; nt < 2; ++nt) {
                int cbase = w * 16 + nt * 8;
                unsigned addr = sbase +
                    ((unsigned)((ks * 16 + krow) * 136 + cbase) << 1);
                ldsm_x2t(Bf[ks][nt][0], Bf[ks][nt][1], addr);
            }
    }

    int ccol0 = w * 16 + (lane & 3) * 2;
    float bx0 = 0.f, by0 = 0.f, bx1 = 0.f, by1 = 0.f;
    if (q == 0) {
        bx0 = gb[ccol0];     by0 = gb[ccol0 + 1];
        bx1 = gb[ccol0 + 8]; by1 = gb[ccol0 + 9];
    } else if (q == 1) {
        bx0 = cb[ccol0];     by0 = cb[ccol0 + 1];
        bx1 = cb[ccol0 + 8]; by1 = cb[ccol0 + 9];
    }

    const int arow = lane & 15;
    const int acol = (lane >> 4) * 8;
    const int off0 = p16_off(q, ccol0);
    const int off1 = p16_off(q, ccol0 + 8);

    for (int mt = blockIdx.x; mt < M_TILES; mt += gridDim.x) {
        __syncthreads();
        {
            int row = tid >> 4, colh = (tid & 15) * 8;
            *(uint4*)&S[row * 136 + colh] =
                *(const uint4*)&g_h16[(size_t)(mt * 16 + row) * 128 + colh];
        }
        __syncthreads();

        float acc0[4] = {0.f, 0.f, 0.f, 0.f};
        float acc1[4] = {0.f, 0.f, 0.f, 0.f};
        #pragma unroll
        for (int ks = 0; ks < 8; ++ks) {
            unsigned a[4];
            unsigned addr = sbase +
                ((unsigned)(arow * 136 + ks * 16 + acol) << 1);
            ldsm_x4(a[0], a[1], a[2], a[3], addr);
            mma16816(acc0, a, Bf[ks][0]);
            mma16816(acc1, a, Bf[ks][1]);
        }

        int r0 = mt * 16 + (lane >> 2);
        size_t base = (size_t)r0 * 512;
        __half2 v;
        v = __floats2half2_rn(acc0[0] + bx0, acc0[1] + by0);
        *(__half2*)&g_P16[base + off0] = v;
        v = __floats2half2_rn(acc1[0] + bx1, acc1[1] + by1);
        *(__half2*)&g_P16[base + off1] = v;
        base += 8 * 512;
        v = __floats2half2_rn(acc0[2] + bx0, acc0[3] + by0);
        *(__half2*)&g_P16[base + off0] = v;
        v = __floats2half2_rn(acc1[2] + bx1, acc1[3] + by1);
        *(__half2*)&g_P16[base + off1] = v;
    }
}

// ---------------------------------------------------------------------------
// Kernel 3: edge stage — interleaved P16: ONE LDG.128 per endpoint per edge.
// fp16 W3 in shared, half2 accumulation, 4 edges/warp iter, red.v4 scatter.
// ---------------------------------------------------------------------------
__global__ __launch_bounds__(128, 10) void edge_kernel(
    const void*  __restrict__ ei,
    const float* __restrict__ ef,
    const float* __restrict__ gw, const float* __restrict__ cw)
{
    // s_w[k][lane] = {g(d0,d1), g(d2,d3), c(d0,d1), c(d2,d3)} as half2s
    __shared__ uint4 s_w[DE][32];

    const int tid    = threadIdx.x;
    const int lane   = tid & 31;
    const int warp   = (blockIdx.x * blockDim.x + tid) >> 5;
    const int nwarps = (gridDim.x * blockDim.x) >> 5;
    const int is64   = g_is64;

    for (int i = tid; i < DE * 32; i += blockDim.x) {
        int k = i >> 5, p = i & 31;
        float4 g = *(const float4*)&gw[(size_t)(256 + k) * 128 + p * 4];
        float4 c = *(const float4*)&cw[(size_t)(256 + k) * 128 + p * 4];
        __half2 g0 = __floats2half2_rn(g.x, g.y);
        __half2 g1 = __floats2half2_rn(g.z, g.w);
        __half2 c0 = __floats2half2_rn(c.x, c.y);
        __half2 c1 = __floats2half2_rn(c.z, c.w);
        s_w[k][p] = make_uint4(*(unsigned*)&g0, *(unsigned*)&g1,
                               *(unsigned*)&c0, *(unsigned*)&c1);
    }
    __syncthreads();

    for (int e = warp * 4; e < N_EDGES; e += nwarps * 4) {
        int s[4], d[4];
        if (is64) {
            const long long* E = (const long long*)ei;
            #pragma unroll
            for (int j = 0; j < 4; ++j) {
                s[j] = (int)E[e + j];
                d[j] = (int)E[N_EDGES + e + j];
            }
        } else {
            const int* E = (const int*)ei;
            #pragma unroll
            for (int j = 0; j < 4; ++j) {
                s[j] = E[e + j];
                d[j] = E[N_EDGES + e + j];
            }
        }

        // 8 independent 16B gathers; accumulators init = g1+g2 / c1+c2
        __half2 rg0[4], rg1[4], rc0[4], rc1[4];
        #pragma unroll
        for (int j = 0; j < 4; ++j) {
            uint4 S4 = *(const uint4*)(g_P16 + (size_t)s[j] * 512 + lane * 8);
            uint4 D4 = *(const uint4*)(g_P16 + (size_t)d[j] * 512 + 256 + lane * 8);
            rg0[j] = __hadd2(*(__half2*)&S4.x, *(__half2*)&D4.x);
            rg1[j] = __hadd2(*(__half2*)&S4.y, *(__half2*)&D4.y);
            rc0[j] = __hadd2(*(__half2*)&S4.z, *(__half2*)&D4.z);
            rc1[j] = __hadd2(*(__half2*)&S4.w, *(__half2*)&D4.w);
        }

        // edge features as replicated half2 for shfl broadcast
        unsigned evu[4];
        #pragma unroll
        for (int j = 0; j < 4; ++j) {
            float ev = (lane < DE) ? ef[(size_t)(e + j) * DE + lane] : 0.f;
            __half2 t = __floats2half2_rn(ev, ev);
            evu[j] = *(unsigned*)&t;
        }

        // rank-10 update in half2; W3 LDS.128 amortized over 4 edges
        #pragma unroll
        for (int k = 0; k < DE; ++k) {
            uint4 wv = s_w[k][lane];
            __half2 wG0 = *(__half2*)&wv.x, wG1 = *(__half2*)&wv.y;
            __half2 wC0 = *(__half2*)&wv.z, wC1 = *(__half2*)&wv.w;
            #pragma unroll
            for (int j = 0; j < 4; ++j) {
                unsigned eku = __shfl_sync(0xffffffffu, evu[j], k);
                __half2 ek2 = *(__half2*)&eku;
                rg0[j] = __hfma2(ek2, wG0, rg0[j]);
                rg1[j] = __hfma2(ek2, wG1, rg1[j]);
                rc0[j] = __hfma2(ek2, wC0, rc0[j]);
                rc1[j] = __hfma2(ek2, wC1, rc1[j]);
            }
        }

        // activations (f32) + scatter; output cols = {4*lane..4*lane+3}
        #pragma unroll
        for (int j = 0; j < 4; ++j) {
            float2 gA = __half22float2(rg0[j]);
            float2 gB = __half22float2(rg1[j]);
            float2 cA = __half22float2(rc0[j]);
            float2 cB = __half22float2(rc1[j]);
            float4 m;
            m.x = sigmoid_f(gA.x) * softplus_f(cA.x);
            m.y = sigmoid_f(gA.y) * softplus_f(cA.y);
            m.z = sigmoid_f(gB.x) * softplus_f(cB.x);
            m.w = sigmoid_f(gB.y) * softplus_f(cB.y);
            float* o = g_agg + (size_t)s[j] * D + lane * 4;
            asm volatile("red.global.add.v4.f32 [%0], {%1,%2,%3,%4};"
                         :: "l"(o), "f"(m.x), "f"(m.y), "f"(m.z), "f"(m.w)
                         : "memory");
        }
    }
}

// ---------------------------------------------------------------------------
// Kernel 4: BN stats (fp64 accumulate)
// ---------------------------------------------------------------------------
__global__ void stats_kernel() {
    int d = threadIdx.x;   // blockDim = 128
    double s = 0.0, s2 = 0.0;
    for (int n = blockIdx.x; n < N_NODES; n += gridDim.x) {
        float v = g_agg[(size_t)n * D + d];
        s  += (double)v;
        s2 += (double)v * (double)v;
    }
    atomicAdd(&g_sum[d], s);
    atomicAdd(&g_sumsq[d], s2);
}

// ---------------------------------------------------------------------------
// Kernel 5: BN affine fold (per-block, in smem) + apply + residual + softplus
// ---------------------------------------------------------------------------
__global__ __launch_bounds__(256) void final_kernel(
    const float* __restrict__ h,
    const float* __restrict__ gamma, const float* __restrict__ beta,
    float* __restrict__ out)
{
    __shared__ float sa[D], sb[D];
    if (threadIdx.x < D) {
        int d = threadIdx.x;
        double mean = g_sum[d] * (1.0 / N_NODES);
        double var  = g_sumsq[d] * (1.0 / N_NODES) - mean * mean;
        float invstd = rsqrtf((float)var + BN_EPS);
        float a = invstd * gamma[d];
        sa[d] = a;
        sb[d] = beta[d] - (float)mean * a;
    }
    __syncthreads();

    const int total4 = N_NODES * D / 4;
    for (int f4 = blockIdx.x * blockDim.x + threadIdx.x; f4 < total4;
         f4 += gridDim.x * blockDim.x) {
        int d4 = (f4 & 31) * 4;
        float4 av = ((const float4*)g_agg)[f4];
        float4 hv = ((const float4*)h)[f4];
        float4 aa = *(const float4*)&sa[d4];
        float4 bb = *(const float4*)&sb[d4];
        float4 r;
        r.x = softplus_f(hv.x + av.x * aa.x + bb.x);
        r.y = softplus_f(hv.y + av.y * aa.y + bb.y);
        r.z = softplus_f(hv.z + av.z * aa.z + bb.z);
        r.w = softplus_f(hv.w + av.w * aa.w + bb.w);
        ((float4*)out)[f4] = r;
    }
}

// ---------------------------------------------------------------------------
extern "C" void kernel_launch(void* const* d_in, const int* in_sizes, int n_in,
                              void* d_out, int out_size) {
    const float* h     = (const float*)d_in[0];
    const void*  ei    = d_in[1];
    const float* ef    = (const float*)d_in[2];
    const float* gw    = (const float*)d_in[3];
    const float* gb    = (const float*)d_in[4];
    const float* cw    = (const float*)d_in[5];
    const float* cb    = (const float*)d_in[6];
    const float* gamma = (const float*)d_in[7];
    const float* beta  = (const float*)d_in[8];
    float* out = (float*)d_out;

    prep_kernel<<<1024, 256>>>(h, gw, cw, (const int*)ei);
    dim3 gg(782, 4);
    node_gemm_tc<<<gg, 256>>>(gb, cb);
    edge_kernel<<<4096, 128>>>(ei, ef, gw, cw);
    stats_kernel<<<2048, 128>>>();
    final_kernel<<<1024, 256>>>(h, gamma, beta, out);
}

// round 11
// speedup vs baseline: 17.7013x; 1.1676x over previous
#include <cuda_runtime.h>
#include <cuda_fp16.h>
#include <math.h>

#define N_NODES 50000
#define N_EDGES 800000
#define D       128
#define DE      10
#define BN_EPS  1e-5f
#define M_TILES 3125          // 50000 / 16

typedef unsigned long long ull;

// Scratch (device globals: allocation-free)
// P16 per node: 512 halves in two 256-half blocks.
//   src block [0:256):  granule l (l=0..31) = {g1[4l..4l+3], c1[4l..4l+3]}
//   dst block [256:512): granule l = {g2[4l..4l+3], c2[4l..4l+3]}
__device__ __half  g_P16[N_NODES * 512];
__device__ __half  g_h16[N_NODES * D];
__device__ __half  g_w16[4 * 128 * 128];   // [q][k][c]
__device__ float   g_agg[N_NODES * D];
__device__ double  g_sum[D];
__device__ double  g_sumsq[D];
__device__ int     g_is64;

__device__ __forceinline__ float softplus_f(float x) {
    return fmaxf(x, 0.0f) + __logf(1.0f + __expf(-fabsf(x)));
}
__device__ __forceinline__ float sigmoid_f(float x) {
    // 1 MUFU via tanh.approx (vs ex2 + fp32 division)
    float y;
    asm("tanh.approx.f32 %0, %1;" : "=f"(y) : "f"(0.5f * x));
    return fmaf(0.5f, y, 0.5f);
}

// ---- mma / ldmatrix wrappers ----
__device__ __forceinline__ unsigned smem_u32(const void* p) {
    return (unsigned)__cvta_generic_to_shared(p);
}
__device__ __forceinline__ void ldsm_x4(unsigned& a0, unsigned& a1,
                                        unsigned& a2, unsigned& a3, unsigned addr) {
    asm volatile("ldmatrix.sync.aligned.m8n8.x4.shared.b16 {%0,%1,%2,%3}, [%4];"
                 : "=r"(a0), "=r"(a1), "=r"(a2), "=r"(a3) : "r"(addr));
}
__device__ __forceinline__ void ldsm_x2t(unsigned& b0, unsigned& b1, unsigned addr) {
    asm volatile("ldmatrix.sync.aligned.m8n8.x2.trans.shared.b16 {%0,%1}, [%2];"
                 : "=r"(b0), "=r"(b1) : "r"(addr));
}
__device__ __forceinline__ void mma16816(float* d, const unsigned* a, const unsigned* b) {
    asm volatile(
        "mma.sync.aligned.m16n8k16.row.col.f32.f16.f16.f32 "
        "{%0,%1,%2,%3}, {%4,%5,%6,%7}, {%8,%9}, {%0,%1,%2,%3};"
        : "+f"(d[0]), "+f"(d[1]), "+f"(d[2]), "+f"(d[3])
        : "r"(a[0]), "r"(a[1]), "r"(a[2]), "r"(a[3]), "r"(b[0]), "r"(b[1]));
}

// P16 offset for logical (quadrant q, channel d) within a node's 512 halves
__device__ __host__ __forceinline__ int p16_off(int q, int d) {
    return ((q >> 1) ? 256 : 0) + (d >> 2) * 8 + ((q & 1) ? 4 : 0) + (d & 3);
}

// ---------------------------------------------------------------------------
// Kernel 1: zero agg + stats + convert h -> fp16 + convert W -> fp16 + detect
// ---------------------------------------------------------------------------
__global__ void prep_kernel(const float* __restrict__ h,
                            const float* __restrict__ gw,
                            const float* __restrict__ cw,
                            const int* __restrict__ ei32) {
    const int total4 = N_NODES * D / 4;
    float4 z = make_float4(0.f, 0.f, 0.f, 0.f);
    int gid = blockIdx.x * blockDim.x + threadIdx.x;
    for (int i = gid; i < total4; i += gridDim.x * blockDim.x) {
        ((float4*)g_agg)[i] = z;
        float4 v = ((const float4*)h)[i];
        __half2 a = __floats2half2_rn(v.x, v.y);
        __half2 b = __floats2half2_rn(v.z, v.w);
        ((uint2*)g_h16)[i] = make_uint2(*(unsigned*)&a, *(unsigned*)&b);
    }
    if (gid < 4 * 128 * 128 / 2) {   // 2 elements each
        int i = gid * 2;
        int q = i >> 14, k = (i >> 7) & 127, c = i & 127;
        const float* W = (q & 1) ? cw : gw;
        float2 wv = *(const float2*)&W[(size_t)((q >> 1) * 128 + k) * 128 + c];
        *(__half2*)&g_w16[i] = __floats2half2_rn(wv.x, wv.y);
    }
    if (gid == 0) {
        int nz = 0;
        #pragma unroll
        for (int j = 0; j < 64; ++j) nz |= ei32[2 * j + 1];
        g_is64 = (nz == 0) ? 1 : 0;
    }
    if (blockIdx.x == 0 && threadIdx.x < D) {
        g_sum[threadIdx.x] = 0.0;
        g_sumsq[threadIdx.x] = 0.0;
    }
}

// ---------------------------------------------------------------------------
// Kernel 2: node projection GEMM on tensor cores (HMMA m16n8k16).
// Epilogue stores into the interleaved P16 layout via p16_off().
// ---------------------------------------------------------------------------
__global__ __launch_bounds__(256) void node_gemm_tc(
    const float* __restrict__ gb, const float* __restrict__ cb)
{
    __shared__ __half S[128 * 136];

    const int q    = blockIdx.y;
    const int tid  = threadIdx.x;
    const int w    = tid >> 5;
    const int lane = tid & 31;
    const unsigned sbase = smem_u32(S);

    const __half* wq = g_w16 + (size_t)q * 16384;
    #pragma unroll
    for (int j = 0; j < 8; ++j) {
        int i = tid + j * 256;
        int row = i >> 4, colh = (i & 15) * 8;
        *(uint4*)&S[row * 136 + colh] = *(const uint4*)&wq[row * 128 + colh];
    }
    __syncthreads();

    unsigned Bf[8][2][2];
    {
        int krow = lane & 15;
        #pragma unroll
        for (int ks = 0; ks < 8; ++ks)
            #pragma unroll
            for (int nt = 0; nt < 2; ++nt) {
                int cbase = w * 16 + nt * 8;
                unsigned addr = sbase +
                    ((unsigned)((ks * 16 + krow) * 136 + cbase) << 1);
                ldsm_x2t(Bf[ks][nt][0], Bf[ks][nt][1], addr);
            }
    }

    int ccol0 = w * 16 + (lane & 3) * 2;
    float bx0 = 0.f, by0 = 0.f, bx1 = 0.f, by1 = 0.f;
    if (q == 0) {
        bx0 = gb[ccol0];     by0 = gb[ccol0 + 1];
        bx1 = gb[ccol0 + 8]; by1 = gb[ccol0 + 9];
    } else if (q == 1) {
        bx0 = cb[ccol0];     by0 = cb[ccol0 + 1];
        bx1 = cb[ccol0 + 8]; by1 = cb[ccol0 + 9];
    }

    const int arow = lane & 15;
    const int acol = (lane >> 4) * 8;
    const int off0 = p16_off(q, ccol0);
    const int off1 = p16_off(q, ccol0 + 8);

    for (int mt = blockIdx.x; mt < M_TILES; mt += gridDim.x) {
        __syncthreads();
        {
            int row = tid >> 4, colh = (tid & 15) * 8;
            *(uint4*)&S[row * 136 + colh] =
                *(const uint4*)&g_h16[(size_t)(mt * 16 + row) * 128 + colh];
        }
        __syncthreads();

        float acc0[4] = {0.f, 0.f, 0.f, 0.f};
        float acc1[4] = {0.f, 0.f, 0.f, 0.f};
        #pragma unroll
        for (int ks = 0; ks < 8; ++ks) {
            unsigned a[4];
            unsigned addr = sbase +
                ((unsigned)(arow * 136 + ks * 16 + acol) << 1);
            ldsm_x4(a[0], a[1], a[2], a[3], addr);
            mma16816(acc0, a, Bf[ks][0]);
            mma16816(acc1, a, Bf[ks][1]);
        }

        int r0 = mt * 16 + (lane >> 2);
        size_t base = (size_t)r0 * 512;
        __half2 v;
        v = __floats2half2_rn(acc0[0] + bx0, acc0[1] + by0);
        *(__half2*)&g_P16[base + off0] = v;
        v = __floats2half2_rn(acc1[0] + bx1, acc1[1] + by1);
        *(__half2*)&g_P16[base + off1] = v;
        base += 8 * 512;
        v = __floats2half2_rn(acc0[2] + bx0, acc0[3] + by0);
        *(__half2*)&g_P16[base + off0] = v;
        v = __floats2half2_rn(acc1[2] + bx1, acc1[3] + by1);
        *(__half2*)&g_P16[base + off1] = v;
    }
}

// ---------------------------------------------------------------------------
// Kernel 3: edge stage — interleaved P16: ONE LDG.128 per endpoint per edge.
// fp16 W3 in shared, half2 accumulation, 4 edges/warp iter, red.v4 scatter.
// ---------------------------------------------------------------------------
__global__ __launch_bounds__(128, 10) void edge_kernel(
    const void*  __restrict__ ei,
    const float* __restrict__ ef,
    const float* __restrict__ gw, const float* __restrict__ cw)
{
    // s_w[k][lane] = {g(d0,d1), g(d2,d3), c(d0,d1), c(d2,d3)} as half2s
    __shared__ uint4 s_w[DE][32];

    const int tid    = threadIdx.x;
    const int lane   = tid & 31;
    const int warp   = (blockIdx.x * blockDim.x + tid) >> 5;
    const int nwarps = (gridDim.x * blockDim.x) >> 5;
    const int is64   = g_is64;

    for (int i = tid; i < DE * 32; i += blockDim.x) {
        int k = i >> 5, p = i & 31;
        float4 g = *(const float4*)&gw[(size_t)(256 + k) * 128 + p * 4];
        float4 c = *(const float4*)&cw[(size_t)(256 + k) * 128 + p * 4];
        __half2 g0 = __floats2half2_rn(g.x, g.y);
        __half2 g1 = __floats2half2_rn(g.z, g.w);
        __half2 c0 = __floats2half2_rn(c.x, c.y);
        __half2 c1 = __floats2half2_rn(c.z, c.w);
        s_w[k][p] = make_uint4(*(unsigned*)&g0, *(unsigned*)&g1,
                               *(unsigned*)&c0, *(unsigned*)&c1);
    }
    __syncthreads();

    for (int e = warp * 4; e < N_EDGES; e += nwarps * 4) {
        int s[4], d[4];
        if (is64) {
            const long long* E = (const long long*)ei;
            #pragma unroll
            for (int j = 0; j < 4; ++j) {
                s[j] = (int)E[e + j];
                d[j] = (int)E[N_EDGES + e + j];
            }
        } else {
            const int* E = (const int*)ei;
            #pragma unroll
            for (int j = 0; j < 4; ++j) {
                s[j] = E[e + j];
                d[j] = E[N_EDGES + e + j];
            }
        }

        // 8 independent 16B gathers; accumulators init = g1+g2 / c1+c2
        __half2 rg0[4], rg1[4], rc0[4], rc1[4];
        #pragma unroll
        for (int j = 0; j < 4; ++j) {
            uint4 S4 = *(const uint4*)(g_P16 + (size_t)s[j] * 512 + lane * 8);
            uint4 D4 = *(const uint4*)(g_P16 + (size_t)d[j] * 512 + 256 + lane * 8);
            rg0[j] = __hadd2(*(__half2*)&S4.x, *(__half2*)&D4.x);
            rg1[j] = __hadd2(*(__half2*)&S4.y, *(__half2*)&D4.y);
            rc0[j] = __hadd2(*(__half2*)&S4.z, *(__half2*)&D4.z);
            rc1[j] = __hadd2(*(__half2*)&S4.w, *(__half2*)&D4.w);
        }

        // edge features as replicated half2 for shfl broadcast
        unsigned evu[4];
        #pragma unroll
        for (int j = 0; j < 4; ++j) {
            float ev = (lane < DE) ? ef[(size_t)(e + j) * DE + lane] : 0.f;
            __half2 t = __floats2half2_rn(ev, ev);
            evu[j] = *(unsigned*)&t;
        }

        // rank-10 update in half2; W3 LDS.128 amortized over 4 edges
        #pragma unroll
        for (int k = 0; k < DE; ++k) {
            uint4 wv = s_w[k][lane];
            __half2 wG0 = *(__half2*)&wv.x, wG1 = *(__half2*)&wv.y;
            __half2 wC0 = *(__half2*)&wv.z, wC1 = *(__half2*)&wv.w;
            #pragma unroll
            for (int j = 0; j < 4; ++j) {
                unsigned eku = __shfl_sync(0xffffffffu, evu[j], k);
                __half2 ek2 = *(__half2*)&eku;
                rg0[j] = __hfma2(ek2, wG0, rg0[j]);
                rg1[j] = __hfma2(ek2, wG1, rg1[j]);
                rc0[j] = __hfma2(ek2, wC0, rc0[j]);
                rc1[j] = __hfma2(ek2, wC1, rc1[j]);
            }
        }

        // activations (f32) + scatter; output cols = {4*lane..4*lane+3}
        #pragma unroll
        for (int j = 0; j < 4; ++j) {
            float2 gA = __half22float2(rg0[j]);
            float2 gB = __half22float2(rg1[j]);
            float2 cA = __half22float2(rc0[j]);
            float2 cB = __half22float2(rc1[j]);
            float4 m;
            m.x = sigmoid_f(gA.x) * softplus_f(cA.x);
            m.y = sigmoid_f(gA.y) * softplus_f(cA.y);
            m.z = sigmoid_f(gB.x) * softplus_f(cB.x);
            m.w = sigmoid_f(gB.y) * softplus_f(cB.y);
            float* o = g_agg + (size_t)s[j] * D + lane * 4;
            asm volatile("red.global.add.v4.f32 [%0], {%1,%2,%3,%4};"
                         :: "l"(o), "f"(m.x), "f"(m.y), "f"(m.z), "f"(m.w)
                         : "memory");
        }
    }
}

// ---------------------------------------------------------------------------
// Kernel 4: BN stats — fp32 4-way ILP partials per block chunk, fp64 only at
// the per-block atomic (512 atomics/address instead of 2048, no fp64 chain).
// ---------------------------------------------------------------------------
__global__ __launch_bounds__(128) void stats_kernel() {
    const int d = threadIdx.x;   // blockDim = 128
    const int chunk = (N_NODES + gridDim.x - 1) / gridDim.x;
    const int n0 = blockIdx.x * chunk;
    const int n1 = min(n0 + chunk, N_NODES);

    float s0 = 0.f, s1 = 0.f, s2 = 0.f, s3 = 0.f;
    float q0 = 0.f, q1 = 0.f, q2 = 0.f, q3 = 0.f;
    int n = n0;
    for (; n + 4 <= n1; n += 4) {
        float v0 = g_agg[(size_t)(n + 0) * D + d];
        float v1 = g_agg[(size_t)(n + 1) * D + d];
        float v2 = g_agg[(size_t)(n + 2) * D + d];
        float v3 = g_agg[(size_t)(n + 3) * D + d];
        s0 += v0; q0 = fmaf(v0, v0, q0);
        s1 += v1; q1 = fmaf(v1, v1, q1);
        s2 += v2; q2 = fmaf(v2, v2, q2);
        s3 += v3; q3 = fmaf(v3, v3, q3);
    }
    for (; n < n1; ++n) {
        float v = g_agg[(size_t)n * D + d];
        s0 += v; q0 = fmaf(v, v, q0);
    }
    double s = (double)((s0 + s1) + (s2 + s3));
    double q = (double)((q0 + q1) + (q2 + q3));
    atomicAdd(&g_sum[d], s);
    atomicAdd(&g_sumsq[d], q);
}

// ---------------------------------------------------------------------------
// Kernel 5: BN affine fold (per-block, in smem) + apply + residual + softplus
// ---------------------------------------------------------------------------
__global__ __launch_bounds__(256) void final_kernel(
    const float* __restrict__ h,
    const float* __restrict__ gamma, const float* __restrict__ beta,
    float* __restrict__ out)
{
    __shared__ float sa[D], sb[D];
    if (threadIdx.x < D) {
        int d = threadIdx.x;
        double mean = g_sum[d] * (1.0 / N_NODES);
        double var  = g_sumsq[d] * (1.0 / N_NODES) - mean * mean;
        float invstd = rsqrtf((float)var + BN_EPS);
        float a = invstd * gamma[d];
        sa[d] = a;
        sb[d] = beta[d] - (float)mean * a;
    }
    __syncthreads();

    const int total4 = N_NODES * D / 4;
    for (int f4 = blockIdx.x * blockDim.x + threadIdx.x; f4 < total4;
         f4 += gridDim.x * blockDim.x) {
        int d4 = (f4 & 31) * 4;
        float4 av = ((const float4*)g_agg)[f4];
        float4 hv = ((const float4*)h)[f4];
        float4 aa = *(const float4*)&sa[d4];
        float4 bb = *(const float4*)&sb[d4];
        float4 r;
        r.x = softplus_f(hv.x + av.x * aa.x + bb.x);
        r.y = softplus_f(hv.y + av.y * aa.y + bb.y);
        r.z = softplus_f(hv.z + av.z * aa.z + bb.z);
        r.w = softplus_f(hv.w + av.w * aa.w + bb.w);
        ((float4*)out)[f4] = r;
    }
}

// ---------------------------------------------------------------------------
extern "C" void kernel_launch(void* const* d_in, const int* in_sizes, int n_in,
                              void* d_out, int out_size) {
    const float* h     = (const float*)d_in[0];
    const void*  ei    = d_in[1];
    const float* ef    = (const float*)d_in[2];
    const float* gw    = (const float*)d_in[3];
    const float* gb    = (const float*)d_in[4];
    const float* cw    = (const float*)d_in[5];
    const float* cb    = (const float*)d_in[6];
    const float* gamma = (const float*)d_in[7];
    const float* beta  = (const float*)d_in[8];
    float* out = (float*)d_out;

    prep_kernel<<<1024, 256>>>(h, gw, cw, (const int*)ei);
    dim3 gg(782, 4);
    node_gemm_tc<<<gg, 256>>>(gb, cb);
    edge_kernel<<<4096, 128>>>(ei, ef, gw, cw);
    stats_kernel<<<512, 128>>>();
    final_kernel<<<1024, 256>>>(h, gamma, beta, out);
}